// round 5
// baseline (speedup 1.0000x reference)
#include <cuda_runtime.h>

// DynamicRelationshipExtractor — GB300 sm_103a, round 4
// Base = round 2 (3245us). Single change: hid-update GEMM retiled to
// warp = 16p x 128q, thread = 4p x 16q with a conflict-free layout:
//   weights: 8 lanes x 16B contiguous 128B, 4-way multicast -> 1 wavefront
//   acts:    4 consecutive rows per lane-group (bank offset 4) -> 1 wavefront
// Halves the hid-loop L1 wavefronts vs round 2.

#define EPSF 1e-6f

static const int NC = 64;
static const int Dd = 128;
static const int Pp = 2016;
static const int TP = 64;

typedef unsigned long long u64;

__device__ __forceinline__ u64 pk2(float x, float y) {
    u64 r; asm("mov.b64 %0, {%1, %2};" : "=l"(r) : "f"(x), "f"(y)); return r;
}
__device__ __forceinline__ u64 dup2(float x) {
    u64 r; asm("mov.b64 %0, {%1, %1};" : "=l"(r) : "f"(x)); return r;
}
__device__ __forceinline__ void fma2(u64 &d, u64 a, u64 b) {
    asm("fma.rn.f32x2 %0, %1, %2, %0;" : "+l"(d) : "l"(a), "l"(b));
}
__device__ __forceinline__ void up2(u64 v, float &x, float &y) {
    asm("mov.b64 {%0, %1}, %2;" : "=f"(x), "=f"(y) : "l"(v));
}

// shared layout (floats)
#define OFF_XS     0
#define OFF_FEATS  (OFF_XS + 64*128)        // 8192, stride 132
#define OFF_TOKB   (OFF_FEATS + 64*132)     // stride 132
#define OFF_HB     (OFF_TOKB + 64*132)      // stride 68
#define OFF_WB     (OFF_HB + 64*68)         // 8192-float weight scratch
#define OFF_PCON   (OFF_WB + 8192)
#define OFF_PTOK4  (OFF_PCON + 4*256)
#define OFF_PH4    (OFF_PTOK4 + 4*128)
#define OFF_INORM  (OFF_PH4 + 4*64)
#define OFF_END    (OFF_INORM + 64)
#define OFF_HID    OFF_FEATS                // alias: 64*260 <= feats+tokb (16896)
#define SMEM_FLOATS OFF_END
#define SMEM_BYTES (SMEM_FLOATS*4 + 3*64*4)

__device__ __forceinline__ float featf(int k, float a, float c, float ni, float nj) {
    switch (k) {
        case 0: return a * c;
        case 1: return a + c;
        case 2: return (a * ni) * (c * nj);
        case 3: return fabsf(a - c);
        case 4: return a - c;
        case 5: return c - a;
        case 6: return __fdiv_rn(a, c + EPSF);
        default: return __fdiv_rn(c, a + EPSF);
    }
}

__global__ void __launch_bounds__(256, 1)
dre_kernel(const float* __restrict__ x, const int* __restrict__ presence,
           const int* __restrict__ idx_i, const int* __restrict__ idx_j,
           const float* __restrict__ oW1, const float* __restrict__ ob1,
           const float* __restrict__ oW2, const float* __restrict__ ob2,
           const float* __restrict__ pW1, const float* __restrict__ pb1,
           const float* __restrict__ pW2, const float* __restrict__ pb2,
           const float* __restrict__ fW1, const float* __restrict__ fb1,
           const float* __restrict__ fW2, const float* __restrict__ fb2,
           float* __restrict__ out)
{
    extern __shared__ float sm[];
    float* xs    = sm + OFF_XS;
    float* feats = sm + OFF_FEATS;
    float* tokb  = sm + OFF_TOKB;
    float* hb    = sm + OFF_HB;
    float* wb    = sm + OFF_WB;
    float* pcon  = sm + OFF_PCON;
    float* ptok4 = sm + OFF_PTOK4;
    float* ph4   = sm + OFF_PH4;
    float* inorm = sm + OFF_INORM;
    int*   pi    = (int*)(sm + OFF_END);
    int*   pj    = pi + 64;
    int*   pcx   = pj + 64;

    const int tid = threadIdx.x;
    const int b   = blockIdx.x >> 5;
    const int p0  = (blockIdx.x & 31) * TP;

    // ---- load x[b] into shared ----
    {
        const float4* src = (const float4*)(x + (size_t)b * NC * Dd);
        float4* dst = (float4*)xs;
        #pragma unroll
        for (int i = 0; i < 8; i++) dst[tid + i*256] = src[tid + i*256];
    }
    // ---- pair indices + presence class ----
    if (tid < TP) {
        int pp = p0 + tid; if (pp >= Pp) pp = Pp - 1;
        int ii = idx_i[pp], jj = idx_j[pp];
        pi[tid] = ii; pj[tid] = jj;
        int pa = presence[b*NC + ii], pb_ = presence[b*NC + jj];
        pcx[tid] = pa ? (pb_ ? 0 : 1) : (pb_ ? 2 : 3);
    }
    // ---- ph4 = relu(pres_W1[c] + pres_b1) ----
    {
        int c = tid >> 6, t = tid & 63;
        float v = pW1[c*64 + t] + pb1[t];
        ph4[tid] = v > 0.f ? v : 0.f;
    }
    __syncthreads();

    // ---- per-column inverse norms ----
    if (tid < NC) {
        float s = 0.f;
        const float* row = xs + tid * Dd;
        #pragma unroll 8
        for (int d = 0; d < Dd; d++) { float v = row[d]; s = fmaf(v, v, s); }
        inorm[tid] = __fdiv_rn(1.f, __fsqrt_rn(s) + EPSF);
    }
    // ---- ptok4 = ph4 @ pres_W2 + pres_b2 ----
    for (int o = tid; o < 512; o += 256) {
        int c = o >> 7, d = o & 127;
        float s = pb2[d];
        const float* ph = ph4 + c*64;
        #pragma unroll 8
        for (int t = 0; t < 64; t++) s = fmaf(ph[t], pW2[t*128 + d], s);
        ptok4[o] = s;
    }
    __syncthreads();
    // ---- pcon = ptok4 @ fus_W1[1024:1152] ----
    for (int o = tid; o < 1024; o += 256) {
        int c = o >> 8, q = o & 255;
        float s = 0.f;
        const float* pt = ptok4 + c*128;
        #pragma unroll 8
        for (int d = 0; d < 128; d++) s = fmaf(pt[d], fW1[(1024 + d)*256 + q], s);
        pcon[o] = s;
    }
    __syncthreads();

    // ---- hid accumulator: warp = 16p x 128q, thread = 4p x 16q ----
    // p rows owned: prow + i*4 (i=0..3); q owned: qh*128 + eb*32 + qq0 (+0..3)
    const int wid  = tid >> 5, lane = tid & 31;
    const int pt   = wid >> 1, qh = wid & 1;
    const int prow = pt*16 + (lane >> 3);
    const int qq0  = (lane & 7) * 4;
    u64 acc[4][4][2];
    #pragma unroll
    for (int i = 0; i < 4; i++) {
        const int c = pcx[prow + i*4];
        #pragma unroll
        for (int eb = 0; eb < 4; eb++) {
            int q = qh*128 + eb*32 + qq0;
            const float* pcr = pcon + c*256 + q;
            acc[i][eb][0] = pk2(fb1[q]   + pcr[0], fb1[q+1] + pcr[1]);
            acc[i][eb][1] = pk2(fb1[q+2] + pcr[2], fb1[q+3] + pcr[3]);
        }
    }

    const int mlp_idx[8] = {0, 1, 2, 3, 4, 4, 5, 5};

    #pragma unroll 1
    for (int k = 0; k < 8; k++) {
        const int w = mlp_idx[k];

        // stage W1_k (128x64) + compute feats
        {
            const float4* src = (const float4*)(oW1 + w*8192);
            float4* dst = (float4*)wb;
            #pragma unroll
            for (int i = 0; i < 8; i++) dst[tid + i*256] = src[tid + i*256];
        }
        #pragma unroll 1
        for (int it = 0; it < 8; it++) {
            int o = tid + it*256;
            int p = o >> 5, d4 = (o & 31) * 4;
            int ci = pi[p], cj = pj[p];
            float4 a4 = *(const float4*)(xs + ci*Dd + d4);
            float4 c4 = *(const float4*)(xs + cj*Dd + d4);
            float ni = inorm[ci], nj = inorm[cj];
            float4 f4;
            f4.x = featf(k, a4.x, c4.x, ni, nj);
            f4.y = featf(k, a4.y, c4.y, ni, nj);
            f4.z = featf(k, a4.z, c4.z, ni, nj);
            f4.w = featf(k, a4.w, c4.w, ni, nj);
            *(float4*)(feats + p*132 + d4) = f4;
        }
        __syncthreads();

        // h = relu(feats @ W1_k + b1_k) : thread = 2p x (2 halves x 4j)
        {
            const int jg = tid & 7, p2 = (tid >> 3) * 2;
            u64 hacc[2][2][2];
            #pragma unroll
            for (int h = 0; h < 2; h++) {
                int j0 = w*64 + h*32 + jg*4;
                u64 b01 = pk2(ob1[j0],   ob1[j0+1]);
                u64 b23 = pk2(ob1[j0+2], ob1[j0+3]);
                hacc[0][h][0] = b01; hacc[0][h][1] = b23;
                hacc[1][h][0] = b01; hacc[1][h][1] = b23;
            }
            #pragma unroll 2
            for (int d = 0; d < 128; d += 4) {
                float4 f0 = *(const float4*)(feats + p2*132 + d);
                float4 f1 = *(const float4*)(feats + (p2+1)*132 + d);
                #pragma unroll
                for (int dd = 0; dd < 4; dd++) {
                    u64 u0 = dup2((&f0.x)[dd]);
                    u64 u1 = dup2((&f1.x)[dd]);
                    #pragma unroll
                    for (int h = 0; h < 2; h++) {
                        ulonglong2 wv = *(const ulonglong2*)(wb + (d+dd)*64 + h*32 + jg*4);
                        fma2(hacc[0][h][0], u0, wv.x);
                        fma2(hacc[0][h][1], u0, wv.y);
                        fma2(hacc[1][h][0], u1, wv.x);
                        fma2(hacc[1][h][1], u1, wv.y);
                    }
                }
            }
            #pragma unroll
            for (int i = 0; i < 2; i++)
                #pragma unroll
                for (int h = 0; h < 2; h++) {
                    float4 v;
                    up2(hacc[i][h][0], v.x, v.y);
                    up2(hacc[i][h][1], v.z, v.w);
                    v.x = v.x > 0.f ? v.x : 0.f;
                    v.y = v.y > 0.f ? v.y : 0.f;
                    v.z = v.z > 0.f ? v.z : 0.f;
                    v.w = v.w > 0.f ? v.w : 0.f;
                    *(float4*)(hb + (p2+i)*68 + h*32 + jg*4) = v;
                }
        }
        __syncthreads();

        // stage W2_k (64x128)
        {
            const float4* src = (const float4*)(oW2 + w*8192);
            float4* dst = (float4*)wb;
            #pragma unroll
            for (int i = 0; i < 8; i++) dst[tid + i*256] = src[tid + i*256];
        }
        __syncthreads();

        // tok = h @ W2_k + b2_k : thread = 2p x (4 quarters x 4d)
        {
            const int dg = tid & 7, p2 = (tid >> 3) * 2;
            u64 tacc[2][4][2];
            #pragma unroll
            for (int qt = 0; qt < 4; qt++) {
                int d0 = w*128 + qt*32 + dg*4;
                u64 b01 = pk2(ob2[d0],   ob2[d0+1]);
                u64 b23 = pk2(ob2[d0+2], ob2[d0+3]);
                tacc[0][qt][0] = b01; tacc[0][qt][1] = b23;
                tacc[1][qt][0] = b01; tacc[1][qt][1] = b23;
            }
            #pragma unroll 1
            for (int jj = 0; jj < 64; jj += 4) {
                float4 h0 = *(const float4*)(hb + p2*68 + jj);
                float4 h1 = *(const float4*)(hb + (p2+1)*68 + jj);
                #pragma unroll
                for (int e = 0; e < 4; e++) {
                    u64 u0 = dup2((&h0.x)[e]);
                    u64 u1 = dup2((&h1.x)[e]);
                    #pragma unroll
                    for (int qt = 0; qt < 4; qt++) {
                        ulonglong2 wv = *(const ulonglong2*)(wb + (jj+e)*128 + qt*32 + dg*4);
                        fma2(tacc[0][qt][0], u0, wv.x);
                        fma2(tacc[0][qt][1], u0, wv.y);
                        fma2(tacc[1][qt][0], u1, wv.x);
                        fma2(tacc[1][qt][1], u1, wv.y);
                    }
                }
            }
            #pragma unroll
            for (int i = 0; i < 2; i++)
                #pragma unroll
                for (int qt = 0; qt < 4; qt++) {
                    float4 v;
                    up2(tacc[i][qt][0], v.x, v.y);
                    up2(tacc[i][qt][1], v.z, v.w);
                    *(float4*)(tokb + (p2+i)*132 + qt*32 + dg*4) = v;
                }
        }
        __syncthreads();

        // hid += tok_k @ fus_W1[k*128:(k+1)*128] (staged in 32-row chunks)
        #pragma unroll 1
        for (int ch = 0; ch < 4; ch++) {
            {
                const float4* src = (const float4*)(fW1 + (size_t)(k*128 + ch*32) * 256);
                float4* dst = (float4*)wb;
                #pragma unroll
                for (int i = 0; i < 8; i++) dst[tid + i*256] = src[tid + i*256];
            }
            __syncthreads();
            #pragma unroll 1
            for (int c4 = 0; c4 < 8; c4++) {
                const int c0 = c4 * 4;
                float4 t[4];
                #pragma unroll
                for (int i = 0; i < 4; i++)
                    t[i] = *(const float4*)(tokb + (prow + i*4)*132 + ch*32 + c0);
                #pragma unroll
                for (int e = 0; e < 4; e++) {
                    const float* wr = wb + (c0+e)*256 + qh*128 + qq0;
                    ulonglong2 w0 = *(const ulonglong2*)(wr);
                    ulonglong2 w1 = *(const ulonglong2*)(wr + 32);
                    ulonglong2 w2 = *(const ulonglong2*)(wr + 64);
                    ulonglong2 w3 = *(const ulonglong2*)(wr + 96);
                    #pragma unroll
                    for (int i = 0; i < 4; i++) {
                        u64 tv = dup2((&t[i].x)[e]);
                        fma2(acc[i][0][0], tv, w0.x);
                        fma2(acc[i][0][1], tv, w0.y);
                        fma2(acc[i][1][0], tv, w1.x);
                        fma2(acc[i][1][1], tv, w1.y);
                        fma2(acc[i][2][0], tv, w2.x);
                        fma2(acc[i][2][1], tv, w2.y);
                        fma2(acc[i][3][0], tv, w3.x);
                        fma2(acc[i][3][1], tv, w3.y);
                    }
                }
            }
            __syncthreads();
        }
    }

    // ---- relu(acc) -> hid (aliased over feats+tokb), stride 260 ----
    float* hid = sm + OFF_HID;
    #pragma unroll
    for (int i = 0; i < 4; i++) {
        float* hrow = hid + (prow + i*4)*260 + qh*128 + qq0;
        #pragma unroll
        for (int eb = 0; eb < 4; eb++) {
            float4 v;
            up2(acc[i][eb][0], v.x, v.y);
            up2(acc[i][eb][1], v.z, v.w);
            v.x = v.x > 0.f ? v.x : 0.f;
            v.y = v.y > 0.f ? v.y : 0.f;
            v.z = v.z > 0.f ? v.z : 0.f;
            v.w = v.w > 0.f ? v.w : 0.f;
            *(float4*)(hrow + eb*32) = v;
        }
    }
    __syncthreads();

    // ---- out = relu(hid) @ fus_W2 + fus_b2 : thread = 2p x (4 quarters x 4d) ----
    {
        const int dg = tid & 7, p2 = (tid >> 3) * 2;
        u64 oacc[2][4][2];
        #pragma unroll
        for (int qt = 0; qt < 4; qt++) {
            int d0 = qt*32 + dg*4;
            u64 b01 = pk2(fb2[d0],   fb2[d0+1]);
            u64 b23 = pk2(fb2[d0+2], fb2[d0+3]);
            oacc[0][qt][0] = b01; oacc[0][qt][1] = b23;
            oacc[1][qt][0] = b01; oacc[1][qt][1] = b23;
        }
        #pragma unroll 1
        for (int ch = 0; ch < 4; ch++) {
            {
                const float4* src = (const float4*)(fW2 + (size_t)ch * 64 * 128);
                float4* dst = (float4*)wb;
                #pragma unroll
                for (int i = 0; i < 8; i++) dst[tid + i*256] = src[tid + i*256];
            }
            __syncthreads();
            #pragma unroll 1
            for (int qq = 0; qq < 64; qq += 4) {
                float4 h0 = *(const float4*)(hid + p2*260 + ch*64 + qq);
                float4 h1 = *(const float4*)(hid + (p2+1)*260 + ch*64 + qq);
                #pragma unroll
                for (int e = 0; e < 4; e++) {
                    u64 u0 = dup2((&h0.x)[e]);
                    u64 u1 = dup2((&h1.x)[e]);
                    #pragma unroll
                    for (int qt = 0; qt < 4; qt++) {
                        ulonglong2 wv = *(const ulonglong2*)(wb + (qq+e)*128 + qt*32 + dg*4);
                        fma2(oacc[0][qt][0], u0, wv.x);
                        fma2(oacc[0][qt][1], u0, wv.y);
                        fma2(oacc[1][qt][0], u1, wv.x);
                        fma2(oacc[1][qt][1], u1, wv.y);
                    }
                }
            }
            __syncthreads();
        }
        #pragma unroll
        for (int i = 0; i < 2; i++) {
            int p = p2 + i;
            if (p0 + p < Pp) {
                float* orow = out + ((size_t)(b*Pp + p0 + p)) * 128;
                #pragma unroll
                for (int qt = 0; qt < 4; qt++) {
                    float4 v;
                    up2(oacc[i][qt][0], v.x, v.y);
                    up2(oacc[i][qt][1], v.z, v.w);
                    *(float4*)(orow + qt*32 + dg*4) = v;
                }
            }
        }
    }
}

extern "C" void kernel_launch(void* const* d_in, const int* in_sizes, int n_in,
                              void* d_out, int out_size) {
    const float* x        = (const float*)d_in[0];
    const int*   presence = (const int*)d_in[1];
    const int*   idx_i    = (const int*)d_in[2];
    const int*   idx_j    = (const int*)d_in[3];
    const float* oW1      = (const float*)d_in[4];
    const float* ob1      = (const float*)d_in[5];
    const float* oW2      = (const float*)d_in[6];
    const float* ob2      = (const float*)d_in[7];
    const float* pW1      = (const float*)d_in[8];
    const float* pb1      = (const float*)d_in[9];
    const float* pW2      = (const float*)d_in[10];
    const float* pb2      = (const float*)d_in[11];
    const float* fW1      = (const float*)d_in[12];
    const float* fb1      = (const float*)d_in[13];
    const float* fW2      = (const float*)d_in[14];
    const float* fb2      = (const float*)d_in[15];

    cudaFuncSetAttribute(dre_kernel, cudaFuncAttributeMaxDynamicSharedMemorySize, SMEM_BYTES);
    dre_kernel<<<2048, 256, SMEM_BYTES>>>(x, presence, idx_i, idx_j,
                                          oW1, ob1, oW2, ob2,
                                          pW1, pb1, pW2, pb2,
                                          fW1, fb1, fW2, fb2,
                                          (float*)d_out);
}

// round 7
// speedup vs baseline: 1.2158x; 1.2158x over previous
#include <cuda_runtime.h>
#include <cuda_bf16.h>
#include <cstdint>

// DynamicRelationshipExtractor — GB300 sm_103a, round 7
// Round-4 skeleton + hid-update GEMM (66% of MACs) on mma.sync.m16n8k16.bf16
// (HMMA fallback — tcgen05 unavailable at the harness's compute_103 PTX target),
// 3-term bf16 split precision. h/tok/fusion2 stay scalar FFMA2 (round-4 code).

#define EPSF 1e-6f

static const int NC = 64;
static const int Dd = 128;
static const int Pp = 2016;
static const int TP = 64;

typedef unsigned long long u64;
typedef unsigned int u32;

__device__ __forceinline__ u64 pk2(float x, float y) {
    u64 r; asm("mov.b64 %0, {%1, %2};" : "=l"(r) : "f"(x), "f"(y)); return r;
}
__device__ __forceinline__ u64 dup2(float x) {
    u64 r; asm("mov.b64 %0, {%1, %1};" : "=l"(r) : "f"(x)); return r;
}
__device__ __forceinline__ void fma2(u64 &d, u64 a, u64 b) {
    asm("fma.rn.f32x2 %0, %1, %2, %0;" : "+l"(d) : "l"(a), "l"(b));
}
__device__ __forceinline__ void up2(u64 v, float &x, float &y) {
    asm("mov.b64 {%0, %1}, %2;" : "=f"(x), "=f"(y) : "l"(v));
}
__device__ __forceinline__ void mma16816(float* c, u32 a0, u32 a1, u32 a2, u32 a3,
                                         u32 b0, u32 b1) {
    asm volatile(
        "mma.sync.aligned.m16n8k16.row.col.f32.bf16.bf16.f32 "
        "{%0,%1,%2,%3},{%4,%5,%6,%7},{%8,%9},{%0,%1,%2,%3};"
        : "+f"(c[0]), "+f"(c[1]), "+f"(c[2]), "+f"(c[3])
        : "r"(a0), "r"(a1), "r"(a2), "r"(a3), "r"(b0), "r"(b1));
}

// split fp32 pair -> packed bf16 hi pair + lo pair
__device__ __forceinline__ void split2(float a, float b, u32 &hp, u32 &lp) {
    __nv_bfloat16 ha = __float2bfloat16(a), hb_ = __float2bfloat16(b);
    __nv_bfloat16 la = __float2bfloat16(a - __bfloat162float(ha));
    __nv_bfloat16 lb = __float2bfloat16(b - __bfloat162float(hb_));
    hp = ((u32)__bfloat16_as_ushort(hb_) << 16) | (u32)__bfloat16_as_ushort(ha);
    lp = ((u32)__bfloat16_as_ushort(lb)  << 16) | (u32)__bfloat16_as_ushort(la);
}

// fW1^T hi/lo images: [kphase][copy][n=256][k=128], k contiguous
__device__ __align__(16) __nv_bfloat16 g_fw1t[8][2][32768];

__global__ void conv_kernel(const float* __restrict__ fW1) {
    int idx = blockIdx.x * blockDim.x + threadIdx.x;   // 0..262143
    int kp = idx >> 15;
    int e  = idx & 32767;
    int n  = e >> 7, kk = e & 127;
    float v = fW1[(size_t)(kp*128 + kk) * 256 + n];
    __nv_bfloat16 hi = __float2bfloat16(v);
    __nv_bfloat16 lo = __float2bfloat16(v - __bfloat162float(hi));
    g_fw1t[kp][0][n*128 + kk] = hi;
    g_fw1t[kp][1][n*128 + kk] = lo;
}

// ---- shared layout (float offsets) ----
#define OFF_XS     0            // 8192
#define OFF_FEATS  8192         // 64*132 = 8448 -> 16640
#define OFF_HB     16640        // 64*68 = 4352 -> 20992
#define OFF_WB     20992        // 8192 -> 29184
#define OFF_PCON   29184        // 1024 -> 30208
#define OFF_PTOK4  30208        // 512 -> 30720
#define OFF_PH4    30720        // 256 -> 30976
#define OFF_INORM  30976        // 64 -> 31040
#define OFF_INTS   31040        // 192 -> 31232
#define OFF_TOKH   31232        // 64*136 bf16 = 4352 fl -> 35584
#define OFF_TOKL   35584        // 4352 -> 39936
#define OFF_BM     39936        // 256*72 bf16 = 9216 fl -> 49152
#define SMEM_FLOATS 49152
#define SMEM_BYTES  (SMEM_FLOATS * 4)
#define OFF_HID    0            // alias over xs+feats: 64*260 = 16640 fits exactly

__device__ __forceinline__ float featf(int k, float a, float c, float ni, float nj) {
    switch (k) {
        case 0: return a * c;
        case 1: return a + c;
        case 2: return (a * ni) * (c * nj);
        case 3: return fabsf(a - c);
        case 4: return a - c;
        case 5: return c - a;
        case 6: return __fdiv_rn(a, c + EPSF);
        default: return __fdiv_rn(c, a + EPSF);
    }
}

__global__ void __launch_bounds__(256, 1)
dre_kernel(const float* __restrict__ x, const int* __restrict__ presence,
           const int* __restrict__ idx_i, const int* __restrict__ idx_j,
           const float* __restrict__ oW1, const float* __restrict__ ob1,
           const float* __restrict__ oW2, const float* __restrict__ ob2,
           const float* __restrict__ pW1, const float* __restrict__ pb1,
           const float* __restrict__ pW2, const float* __restrict__ pb2,
           const float* __restrict__ fW1, const float* __restrict__ fb1,
           const float* __restrict__ fW2, const float* __restrict__ fb2,
           float* __restrict__ out)
{
    extern __shared__ float sm[];
    float* xs    = sm + OFF_XS;
    float* feats = sm + OFF_FEATS;
    float* hb    = sm + OFF_HB;
    float* wb    = sm + OFF_WB;
    float* pcon  = sm + OFF_PCON;
    float* ptok4 = sm + OFF_PTOK4;
    float* ph4   = sm + OFF_PH4;
    float* inorm = sm + OFF_INORM;
    int*   pi    = (int*)(sm + OFF_INTS);
    int*   pj    = pi + 64;
    int*   pcx   = pj + 64;
    __nv_bfloat16* tokh = (__nv_bfloat16*)(sm + OFF_TOKH);   // [64][136]
    __nv_bfloat16* tokl = (__nv_bfloat16*)(sm + OFF_TOKL);   // [64][136]
    __nv_bfloat16* bm   = (__nv_bfloat16*)(sm + OFF_BM);     // [256][72]

    const int tid = threadIdx.x;
    const int b   = blockIdx.x >> 5;
    const int p0  = (blockIdx.x & 31) * TP;

    // ---- load x[b] into shared ----
    {
        const float4* src = (const float4*)(x + (size_t)b * NC * Dd);
        float4* dst = (float4*)xs;
        #pragma unroll
        for (int i = 0; i < 8; i++) dst[tid + i*256] = src[tid + i*256];
    }
    // ---- pair indices + presence class ----
    if (tid < TP) {
        int pp = p0 + tid; if (pp >= Pp) pp = Pp - 1;
        int ii = idx_i[pp], jj = idx_j[pp];
        pi[tid] = ii; pj[tid] = jj;
        int pa = presence[b*NC + ii], pb_ = presence[b*NC + jj];
        pcx[tid] = pa ? (pb_ ? 0 : 1) : (pb_ ? 2 : 3);
    }
    // ---- ph4 = relu(pres_W1[c] + pres_b1) ----
    {
        int c = tid >> 6, t = tid & 63;
        float v = pW1[c*64 + t] + pb1[t];
        ph4[tid] = v > 0.f ? v : 0.f;
    }
    __syncthreads();

    // ---- per-column inverse norms ----
    if (tid < NC) {
        float s = 0.f;
        const float* row = xs + tid * Dd;
        #pragma unroll 8
        for (int d = 0; d < Dd; d++) { float v = row[d]; s = fmaf(v, v, s); }
        inorm[tid] = __fdiv_rn(1.f, __fsqrt_rn(s) + EPSF);
    }
    // ---- ptok4 = ph4 @ pres_W2 + pres_b2 ----
    for (int o = tid; o < 512; o += 256) {
        int c = o >> 7, d = o & 127;
        float s = pb2[d];
        const float* ph = ph4 + c*64;
        #pragma unroll 8
        for (int t = 0; t < 64; t++) s = fmaf(ph[t], pW2[t*128 + d], s);
        ptok4[o] = s;
    }
    __syncthreads();
    // ---- pcon = ptok4 @ fus_W1[1024:1152] ----
    for (int o = tid; o < 1024; o += 256) {
        int c = o >> 8, q = o & 255;
        float s = 0.f;
        const float* pt = ptok4 + c*128;
        #pragma unroll 8
        for (int d = 0; d < 128; d++) s = fmaf(pt[d], fW1[(size_t)(1024 + d)*256 + q], s);
        pcon[o] = s;
    }
    __syncthreads();

    // ---- hid accumulator as mma fragments ----
    // warp: mtile = wid>>1 (16 rows), nhalf = wid&1 (128 cols). thread: 16 ntiles x 4 f32.
    const int wid  = tid >> 5, lane = tid & 31;
    const int mtile = wid >> 1, nhalf = wid & 1;
    const int gID = lane >> 2;            // 0..7
    const int kq  = (lane & 3) * 2;       // frag col/k element offset
    const int arow = mtile*16 + gID;      // frag rows arow, arow+8
    float acc[16][4];
    {
        const int c0 = pcx[arow], c1 = pcx[arow + 8];
        #pragma unroll
        for (int nt = 0; nt < 16; nt++) {
            int q = nhalf*128 + nt*8 + kq;
            acc[nt][0] = fb1[q]   + pcon[c0*256 + q];
            acc[nt][1] = fb1[q+1] + pcon[c0*256 + q + 1];
            acc[nt][2] = fb1[q]   + pcon[c1*256 + q];
            acc[nt][3] = fb1[q+1] + pcon[c1*256 + q + 1];
        }
    }

    const int mlp_idx[8] = {0, 1, 2, 3, 4, 4, 5, 5};

    #pragma unroll 1
    for (int k = 0; k < 8; k++) {
        const int w = mlp_idx[k];

        // stage W1_k (128x64 fp32) + compute feats
        {
            const float4* src = (const float4*)(oW1 + w*8192);
            float4* dst = (float4*)wb;
            #pragma unroll
            for (int i = 0; i < 8; i++) dst[tid + i*256] = src[tid + i*256];
        }
        #pragma unroll 1
        for (int it = 0; it < 8; it++) {
            int o = tid + it*256;
            int p = o >> 5, d4 = (o & 31) * 4;
            int ci = pi[p], cj = pj[p];
            float4 a4 = *(const float4*)(xs + ci*Dd + d4);
            float4 c4 = *(const float4*)(xs + cj*Dd + d4);
            float ni = inorm[ci], nj = inorm[cj];
            float4 f4;
            f4.x = featf(k, a4.x, c4.x, ni, nj);
            f4.y = featf(k, a4.y, c4.y, ni, nj);
            f4.z = featf(k, a4.z, c4.z, ni, nj);
            f4.w = featf(k, a4.w, c4.w, ni, nj);
            *(float4*)(feats + p*132 + d4) = f4;
        }
        __syncthreads();

        // h = relu(feats @ W1_k + b1_k)
        {
            const int jg = tid & 7, p2 = (tid >> 3) * 2;
            u64 hacc[2][2][2];
            #pragma unroll
            for (int h = 0; h < 2; h++) {
                int j0 = w*64 + h*32 + jg*4;
                u64 b01 = pk2(ob1[j0],   ob1[j0+1]);
                u64 b23 = pk2(ob1[j0+2], ob1[j0+3]);
                hacc[0][h][0] = b01; hacc[0][h][1] = b23;
                hacc[1][h][0] = b01; hacc[1][h][1] = b23;
            }
            #pragma unroll 2
            for (int d = 0; d < 128; d += 4) {
                float4 f0 = *(const float4*)(feats + p2*132 + d);
                float4 f1 = *(const float4*)(feats + (p2+1)*132 + d);
                #pragma unroll
                for (int dd = 0; dd < 4; dd++) {
                    u64 u0 = dup2((&f0.x)[dd]);
                    u64 u1 = dup2((&f1.x)[dd]);
                    #pragma unroll
                    for (int h = 0; h < 2; h++) {
                        ulonglong2 wv = *(const ulonglong2*)(wb + (d+dd)*64 + h*32 + jg*4);
                        fma2(hacc[0][h][0], u0, wv.x);
                        fma2(hacc[0][h][1], u0, wv.y);
                        fma2(hacc[1][h][0], u1, wv.x);
                        fma2(hacc[1][h][1], u1, wv.y);
                    }
                }
            }
            #pragma unroll
            for (int i = 0; i < 2; i++)
                #pragma unroll
                for (int h = 0; h < 2; h++) {
                    float4 v;
                    up2(hacc[i][h][0], v.x, v.y);
                    up2(hacc[i][h][1], v.z, v.w);
                    v.x = v.x > 0.f ? v.x : 0.f;
                    v.y = v.y > 0.f ? v.y : 0.f;
                    v.z = v.z > 0.f ? v.z : 0.f;
                    v.w = v.w > 0.f ? v.w : 0.f;
                    *(float4*)(hb + (p2+i)*68 + h*32 + jg*4) = v;
                }
        }
        __syncthreads();

        // stage W2_k (64x128 fp32)
        {
            const float4* src = (const float4*)(oW2 + w*8192);
            float4* dst = (float4*)wb;
            #pragma unroll
            for (int i = 0; i < 8; i++) dst[tid + i*256] = src[tid + i*256];
        }
        __syncthreads();

        // tok = h @ W2_k + b2_k ; epilogue -> bf16 hi/lo panels [64][136]
        {
            const int dg = tid & 7, p2 = (tid >> 3) * 2;
            u64 tacc[2][4][2];
            #pragma unroll
            for (int qt = 0; qt < 4; qt++) {
                int d0 = w*128 + qt*32 + dg*4;
                u64 b01 = pk2(ob2[d0],   ob2[d0+1]);
                u64 b23 = pk2(ob2[d0+2], ob2[d0+3]);
                tacc[0][qt][0] = b01; tacc[0][qt][1] = b23;
                tacc[1][qt][0] = b01; tacc[1][qt][1] = b23;
            }
            #pragma unroll 1
            for (int jj = 0; jj < 64; jj += 4) {
                float4 h0 = *(const float4*)(hb + p2*68 + jj);
                float4 h1 = *(const float4*)(hb + (p2+1)*68 + jj);
                #pragma unroll
                for (int e = 0; e < 4; e++) {
                    u64 u0 = dup2((&h0.x)[e]);
                    u64 u1 = dup2((&h1.x)[e]);
                    #pragma unroll
                    for (int qt = 0; qt < 4; qt++) {
                        ulonglong2 wv = *(const ulonglong2*)(wb + (jj+e)*128 + qt*32 + dg*4);
                        fma2(tacc[0][qt][0], u0, wv.x);
                        fma2(tacc[0][qt][1], u0, wv.y);
                        fma2(tacc[1][qt][0], u1, wv.x);
                        fma2(tacc[1][qt][1], u1, wv.y);
                    }
                }
            }
            #pragma unroll
            for (int i = 0; i < 2; i++) {
                int r = p2 + i;
                #pragma unroll
                for (int qt = 0; qt < 4; qt++) {
                    float4 v;
                    up2(tacc[i][qt][0], v.x, v.y);
                    up2(tacc[i][qt][1], v.z, v.w);
                    u32 h01, l01, h23, l23;
                    split2(v.x, v.y, h01, l01);
                    split2(v.z, v.w, h23, l23);
                    int col = qt*32 + dg*4;
                    *(uint2*)(tokh + r*136 + col) = make_uint2(h01, h23);
                    *(uint2*)(tokl + r*136 + col) = make_uint2(l01, l23);
                }
            }
        }
        __syncthreads();

        // hid-update via mma.sync: acc += tok_split @ fW1_k (3-term bf16)
        #pragma unroll 1
        for (int kc = 0; kc < 2; kc++) {
            #pragma unroll 1
            for (int copy = 0; copy < 2; copy++) {
                // stage B chunk [256 n][64 k] -> bm [256][72]
                {
                    const __nv_bfloat16* src = &g_fw1t[k][copy][0] + kc*64;
                    #pragma unroll
                    for (int i = 0; i < 8; i++) {
                        int idx = tid + i*256;
                        int n = idx >> 3, c8 = idx & 7;
                        float4 v = *(const float4*)(src + n*128 + c8*8);
                        *(float4*)(bm + n*72 + c8*8) = v;
                    }
                }
                __syncthreads();
                // mma over 4 local ksteps x 16 ntiles
                #pragma unroll 1
                for (int ks = 0; ks < 4; ks++) {
                    const int k0g = kc*64 + ks*16 + kq;   // global k in tok
                    const int k0l = ks*16 + kq;           // local k in bm
                    u32 ah0 = *(const u32*)(tokh + arow*136 + k0g);
                    u32 ah1 = *(const u32*)(tokh + (arow+8)*136 + k0g);
                    u32 ah2 = *(const u32*)(tokh + arow*136 + k0g + 8);
                    u32 ah3 = *(const u32*)(tokh + (arow+8)*136 + k0g + 8);
                    u32 al0 = 0, al1 = 0, al2 = 0, al3 = 0;
                    if (copy == 0) {
                        al0 = *(const u32*)(tokl + arow*136 + k0g);
                        al1 = *(const u32*)(tokl + (arow+8)*136 + k0g);
                        al2 = *(const u32*)(tokl + arow*136 + k0g + 8);
                        al3 = *(const u32*)(tokl + (arow+8)*136 + k0g + 8);
                    }
                    #pragma unroll
                    for (int nt = 0; nt < 16; nt++) {
                        const int bn = nhalf*128 + nt*8 + gID;
                        u32 b0 = *(const u32*)(bm + bn*72 + k0l);
                        u32 b1 = *(const u32*)(bm + bn*72 + k0l + 8);
                        mma16816(acc[nt], ah0, ah1, ah2, ah3, b0, b1);
                        if (copy == 0)
                            mma16816(acc[nt], al0, al1, al2, al3, b0, b1);
                    }
                }
                __syncthreads();
            }
        }
    }

    // ---- relu(acc) -> hid (alias over xs+feats), stride 260 ----
    float* hid = sm + OFF_HID;
    __syncthreads();
    #pragma unroll
    for (int nt = 0; nt < 16; nt++) {
        int q = nhalf*128 + nt*8 + kq;
        float2 v0, v1;
        v0.x = acc[nt][0] > 0.f ? acc[nt][0] : 0.f;
        v0.y = acc[nt][1] > 0.f ? acc[nt][1] : 0.f;
        v1.x = acc[nt][2] > 0.f ? acc[nt][2] : 0.f;
        v1.y = acc[nt][3] > 0.f ? acc[nt][3] : 0.f;
        *(float2*)(hid + arow*260 + q)     = v0;
        *(float2*)(hid + (arow+8)*260 + q) = v1;
    }
    __syncthreads();

    // ---- out = relu(hid) @ fus_W2 + fus_b2 : thread = 2p x (4 quarters x 4d) ----
    {
        const int dg = tid & 7, p2 = (tid >> 3) * 2;
        u64 oacc[2][4][2];
        #pragma unroll
        for (int qt = 0; qt < 4; qt++) {
            int d0 = qt*32 + dg*4;
            u64 b01 = pk2(fb2[d0],   fb2[d0+1]);
            u64 b23 = pk2(fb2[d0+2], fb2[d0+3]);
            oacc[0][qt][0] = b01; oacc[0][qt][1] = b23;
            oacc[1][qt][0] = b01; oacc[1][qt][1] = b23;
        }
        #pragma unroll 1
        for (int ch = 0; ch < 4; ch++) {
            {
                const float4* src = (const float4*)(fW2 + (size_t)ch * 64 * 128);
                float4* dst = (float4*)wb;
                #pragma unroll
                for (int i = 0; i < 8; i++) dst[tid + i*256] = src[tid + i*256];
            }
            __syncthreads();
            #pragma unroll 1
            for (int qq = 0; qq < 64; qq += 4) {
                float4 h0 = *(const float4*)(hid + p2*260 + ch*64 + qq);
                float4 h1 = *(const float4*)(hid + (p2+1)*260 + ch*64 + qq);
                #pragma unroll
                for (int e = 0; e < 4; e++) {
                    u64 u0 = dup2((&h0.x)[e]);
                    u64 u1 = dup2((&h1.x)[e]);
                    #pragma unroll
                    for (int qt = 0; qt < 4; qt++) {
                        ulonglong2 wv = *(const ulonglong2*)(wb + (qq+e)*128 + qt*32 + dg*4);
                        fma2(oacc[0][qt][0], u0, wv.x);
                        fma2(oacc[0][qt][1], u0, wv.y);
                        fma2(oacc[1][qt][0], u1, wv.x);
                        fma2(oacc[1][qt][1], u1, wv.y);
                    }
                }
            }
            __syncthreads();
        }
        #pragma unroll
        for (int i = 0; i < 2; i++) {
            int p = p2 + i;
            if (p0 + p < Pp) {
                float* orow = out + ((size_t)(b*Pp + p0 + p)) * 128;
                #pragma unroll
                for (int qt = 0; qt < 4; qt++) {
                    float4 v;
                    up2(oacc[i][qt][0], v.x, v.y);
                    up2(oacc[i][qt][1], v.z, v.w);
                    *(float4*)(orow + qt*32 + dg*4) = v;
                }
            }
        }
    }
}

extern "C" void kernel_launch(void* const* d_in, const int* in_sizes, int n_in,
                              void* d_out, int out_size) {
    const float* x        = (const float*)d_in[0];
    const int*   presence = (const int*)d_in[1];
    const int*   idx_i    = (const int*)d_in[2];
    const int*   idx_j    = (const int*)d_in[3];
    const float* oW1      = (const float*)d_in[4];
    const float* ob1      = (const float*)d_in[5];
    const float* oW2      = (const float*)d_in[6];
    const float* ob2      = (const float*)d_in[7];
    const float* pW1      = (const float*)d_in[8];
    const float* pb1      = (const float*)d_in[9];
    const float* pW2      = (const float*)d_in[10];
    const float* pb2      = (const float*)d_in[11];
    const float* fW1      = (const float*)d_in[12];
    const float* fb1      = (const float*)d_in[13];
    const float* fW2      = (const float*)d_in[14];
    const float* fb2      = (const float*)d_in[15];

    conv_kernel<<<1024, 256>>>(fW1);

    cudaFuncSetAttribute(dre_kernel, cudaFuncAttributeMaxDynamicSharedMemorySize, SMEM_BYTES);
    dre_kernel<<<2048, 256, SMEM_BYTES>>>(x, presence, idx_i, idx_j,
                                          oW1, ob1, oW2, ob2,
                                          pW1, pb1, pW2, pb2,
                                          fW1, fb1, fW2, fb2,
                                          (float*)d_out);
}

// round 9
// speedup vs baseline: 1.6184x; 1.3311x over previous
#include <cuda_runtime.h>
#include <cuda_bf16.h>
#include <cstdint>

// DynamicRelationshipExtractor — GB300 sm_103a, round 9
// = round 8 with the h-GEMM W1^T B-fragment stride fixed (36 -> 68 u32;
//   W1^T panels are [64][136] bf16). All three per-phase GEMMs on
//   mma.sync.m16n8k16.bf16 with 3-term split precision.

#define EPSF 1e-6f

static const int NC = 64;
static const int Dd = 128;
static const int Pp = 2016;
static const int TP = 64;

typedef unsigned long long u64;
typedef unsigned int u32;

__device__ __forceinline__ u64 pk2(float x, float y) {
    u64 r; asm("mov.b64 %0, {%1, %2};" : "=l"(r) : "f"(x), "f"(y)); return r;
}
__device__ __forceinline__ u64 dup2(float x) {
    u64 r; asm("mov.b64 %0, {%1, %1};" : "=l"(r) : "f"(x)); return r;
}
__device__ __forceinline__ void fma2(u64 &d, u64 a, u64 b) {
    asm("fma.rn.f32x2 %0, %1, %2, %0;" : "+l"(d) : "l"(a), "l"(b));
}
__device__ __forceinline__ void up2(u64 v, float &x, float &y) {
    asm("mov.b64 {%0, %1}, %2;" : "=f"(x), "=f"(y) : "l"(v));
}
__device__ __forceinline__ void mma16816(float* c, u32 a0, u32 a1, u32 a2, u32 a3,
                                         u32 b0, u32 b1) {
    asm volatile(
        "mma.sync.aligned.m16n8k16.row.col.f32.bf16.bf16.f32 "
        "{%0,%1,%2,%3},{%4,%5,%6,%7},{%8,%9},{%0,%1,%2,%3};"
        : "+f"(c[0]), "+f"(c[1]), "+f"(c[2]), "+f"(c[3])
        : "r"(a0), "r"(a1), "r"(a2), "r"(a3), "r"(b0), "r"(b1));
}

__device__ __forceinline__ void split2(float a, float b, u32 &hp, u32 &lp) {
    __nv_bfloat16 ha = __float2bfloat16(a), hb_ = __float2bfloat16(b);
    __nv_bfloat16 la = __float2bfloat16(a - __bfloat162float(ha));
    __nv_bfloat16 lb = __float2bfloat16(b - __bfloat162float(hb_));
    hp = ((u32)__bfloat16_as_ushort(hb_) << 16) | (u32)__bfloat16_as_ushort(ha);
    lp = ((u32)__bfloat16_as_ushort(lb)  << 16) | (u32)__bfloat16_as_ushort(la);
}

// precomputed weight images (bf16 hi/lo, B-operand [n][k] layouts)
__device__ __align__(16) __nv_bfloat16 g_fw1t[8][2][32768]; // fW1^T [kp]: [256 n][128 k]
__device__ __align__(16) __nv_bfloat16 g_ow1t[6][2][8192];  // W1^T:  [64 n(j)][128 k(d)]
__device__ __align__(16) __nv_bfloat16 g_ow2t[6][2][8192];  // W2^T:  [128 n(d)][64 k(j)]

__global__ void conv_kernel(const float* __restrict__ fW1,
                            const float* __restrict__ oW1,
                            const float* __restrict__ oW2) {
    int idx = blockIdx.x * blockDim.x + threadIdx.x;   // 0..262143
    {
        int kp = idx >> 15;
        int e  = idx & 32767;
        int n  = e >> 7, kk = e & 127;
        float v = fW1[(size_t)(kp*128 + kk) * 256 + n];
        __nv_bfloat16 hi = __float2bfloat16(v);
        __nv_bfloat16 lo = __float2bfloat16(v - __bfloat162float(hi));
        g_fw1t[kp][0][n*128 + kk] = hi;
        g_fw1t[kp][1][n*128 + kk] = lo;
    }
    if (idx < 49152) {
        int w = idx >> 13;
        int e = idx & 8191;
        {
            int n = e >> 7, kk = e & 127;       // n=j, k=d
            float v = oW1[(size_t)w*8192 + kk*64 + n];
            __nv_bfloat16 hi = __float2bfloat16(v);
            __nv_bfloat16 lo = __float2bfloat16(v - __bfloat162float(hi));
            g_ow1t[w][0][n*128 + kk] = hi;
            g_ow1t[w][1][n*128 + kk] = lo;
        }
        {
            int n = e >> 6, kk = e & 63;        // n=d, k=j
            float v = oW2[(size_t)w*8192 + kk*128 + n];
            __nv_bfloat16 hi = __float2bfloat16(v);
            __nv_bfloat16 lo = __float2bfloat16(v - __bfloat162float(hi));
            g_ow2t[w][0][n*64 + kk] = hi;
            g_ow2t[w][1][n*64 + kk] = lo;
        }
    }
}

// ---- shared layout (BYTE offsets) ----
#define OFF_XS     0          // 32768 (fp32 x[b])
#define OFF_FH     32768      // [64][136] bf16 = 17408
#define OFF_FL     50176      // 17408 -> 67584
#define OFF_HH     67584      // [64][72] bf16 = 9216
#define OFF_HL     76800      // 9216 -> 86016
#define OFF_TOKH   86016      // [64][136] = 17408
#define OFF_TOKL   103424     // 17408 -> 120832
#define OFF_WS     120832     // 36864 scratch (W1/W2/fW1 staging, fusion2 fp32)
#define OFF_PCON   157696     // 1024 fl
#define OFF_PTOK4  161792     // 512 fl
#define OFF_PH4    163840     // 256 fl
#define OFF_INORM  164864     // 64 fl
#define OFF_INTS   165120     // 3*64 int
#define SMEM_BYTES 165888
#define OFF_HID    0          // fp32 [64][260] alias over xs+fh+fl (66560 <= 67584)

__device__ __forceinline__ float featf(int k, float a, float c, float ni, float nj) {
    switch (k) {
        case 0: return a * c;
        case 1: return a + c;
        case 2: return (a * ni) * (c * nj);
        case 3: return fabsf(a - c);
        case 4: return a - c;
        case 5: return c - a;
        case 6: return __fdiv_rn(a, c + EPSF);
        default: return __fdiv_rn(c, a + EPSF);
    }
}

__global__ void __launch_bounds__(256, 1)
dre_kernel(const float* __restrict__ x, const int* __restrict__ presence,
           const int* __restrict__ idx_i, const int* __restrict__ idx_j,
           const float* __restrict__ oW1, const float* __restrict__ ob1,
           const float* __restrict__ oW2, const float* __restrict__ ob2,
           const float* __restrict__ pW1, const float* __restrict__ pb1,
           const float* __restrict__ pW2, const float* __restrict__ pb2,
           const float* __restrict__ fW1, const float* __restrict__ fb1,
           const float* __restrict__ fW2, const float* __restrict__ fb2,
           float* __restrict__ out)
{
    extern __shared__ float sm[];
    char*  smc   = (char*)sm;
    float* xs    = (float*)(smc + OFF_XS);
    u32*   fhw   = (u32*)(smc + OFF_FH);
    u32*   flw   = (u32*)(smc + OFF_FL);
    u32*   hhw   = (u32*)(smc + OFF_HH);
    u32*   hlw   = (u32*)(smc + OFF_HL);
    u32*   tokhw = (u32*)(smc + OFF_TOKH);
    u32*   toklw = (u32*)(smc + OFF_TOKL);
    u32*   wsw   = (u32*)(smc + OFF_WS);
    float* pcon  = (float*)(smc + OFF_PCON);
    float* ptok4 = (float*)(smc + OFF_PTOK4);
    float* ph4   = (float*)(smc + OFF_PH4);
    float* inorm = (float*)(smc + OFF_INORM);
    int*   pi    = (int*)(smc + OFF_INTS);
    int*   pj    = pi + 64;
    int*   pcx   = pj + 64;

    const int tid = threadIdx.x;
    const int b   = blockIdx.x >> 5;
    const int p0  = (blockIdx.x & 31) * TP;
    const int wid = tid >> 5, lane = tid & 31;
    const int g   = lane >> 2;          // frag row group 0..7
    const int t   = lane & 3;           // frag k-word 0..3
    const int t2  = t * 2;

    // ---- load x[b] ----
    {
        const float4* src = (const float4*)(x + (size_t)b * NC * Dd);
        float4* dst = (float4*)xs;
        #pragma unroll
        for (int i = 0; i < 8; i++) dst[tid + i*256] = src[tid + i*256];
    }
    if (tid < TP) {
        int pp = p0 + tid; if (pp >= Pp) pp = Pp - 1;
        int ii = idx_i[pp], jj = idx_j[pp];
        pi[tid] = ii; pj[tid] = jj;
        int pa = presence[b*NC + ii], pb_ = presence[b*NC + jj];
        pcx[tid] = pa ? (pb_ ? 0 : 1) : (pb_ ? 2 : 3);
    }
    {
        int c = tid >> 6, tt = tid & 63;
        float v = pW1[c*64 + tt] + pb1[tt];
        ph4[tid] = v > 0.f ? v : 0.f;
    }
    __syncthreads();

    if (tid < NC) {
        float s = 0.f;
        const float* row = xs + tid * Dd;
        #pragma unroll 8
        for (int d = 0; d < Dd; d++) { float v = row[d]; s = fmaf(v, v, s); }
        inorm[tid] = __fdiv_rn(1.f, __fsqrt_rn(s) + EPSF);
    }
    for (int o = tid; o < 512; o += 256) {
        int c = o >> 7, d = o & 127;
        float s = pb2[d];
        const float* ph = ph4 + c*64;
        #pragma unroll 8
        for (int tt = 0; tt < 64; tt++) s = fmaf(ph[tt], pW2[tt*128 + d], s);
        ptok4[o] = s;
    }
    __syncthreads();
    for (int o = tid; o < 1024; o += 256) {
        int c = o >> 8, q = o & 255;
        float s = 0.f;
        const float* pt = ptok4 + c*128;
        #pragma unroll 8
        for (int d = 0; d < 128; d++) s = fmaf(pt[d], fW1[(size_t)(1024 + d)*256 + q], s);
        pcon[o] = s;
    }
    __syncthreads();

    // ---- hid accumulator fragments: warps 2m x 4n ----
    const int mh = wid & 1;        // rows mh*32 .. mh*32+31 (2 mtiles)
    const int nq = wid >> 1;       // cols nq*64 .. nq*64+63 (8 ntiles)
    float acc[2][8][4];
    #pragma unroll
    for (int mt2 = 0; mt2 < 2; mt2++) {
        int row = mh*32 + mt2*16 + g;
        int c0 = pcx[row], c1 = pcx[row + 8];
        #pragma unroll
        for (int nt = 0; nt < 8; nt++) {
            int q = nq*64 + nt*8 + t2;
            acc[mt2][nt][0] = fb1[q]   + pcon[c0*256 + q];
            acc[mt2][nt][1] = fb1[q+1] + pcon[c0*256 + q + 1];
            acc[mt2][nt][2] = fb1[q]   + pcon[c1*256 + q];
            acc[mt2][nt][3] = fb1[q+1] + pcon[c1*256 + q + 1];
        }
    }

    const int mlp_idx[8] = {0, 1, 2, 3, 4, 4, 5, 5};

    #pragma unroll 1
    for (int k = 0; k < 8; k++) {
        const int w = mlp_idx[k];

        // stage W1^T hi/lo into ws: [copy][64][136] bf16
        {
            #pragma unroll
            for (int i = 0; i < 8; i++) {
                int idx = tid + i*256;              // 0..2047 float4
                int c = idx >> 10, e = idx & 1023;
                int n = e >> 4, c8 = e & 15;
                float4 v = *(const float4*)(&g_ow1t[w][c][n*128 + c8*8]);
                *(float4*)(smc + OFF_WS + c*17408 + (n*136 + c8*8)*2) = v;
            }
        }
        // feats -> fh/fl bf16 panels [64][136]
        #pragma unroll 1
        for (int it = 0; it < 8; it++) {
            int o = tid + it*256;
            int p = o >> 5, d4 = (o & 31) * 4;
            int ci = pi[p], cj = pj[p];
            float4 a4 = *(const float4*)(xs + ci*Dd + d4);
            float4 c4 = *(const float4*)(xs + cj*Dd + d4);
            float ni = inorm[ci], nj = inorm[cj];
            float f0 = featf(k, a4.x, c4.x, ni, nj);
            float f1 = featf(k, a4.y, c4.y, ni, nj);
            float f2 = featf(k, a4.z, c4.z, ni, nj);
            float f3 = featf(k, a4.w, c4.w, ni, nj);
            u32 h01, l01, h23, l23;
            split2(f0, f1, h01, l01);
            split2(f2, f3, h23, l23);
            int widx = p*68 + d4/2;
            *(uint2*)(fhw + widx) = make_uint2(h01, h23);
            *(uint2*)(flw + widx) = make_uint2(l01, l23);
        }
        __syncthreads();

        // ---- h = relu(feats @ W1 + b1) via mma: warps 4m x 2n(32) ----
        {
            const int mt = wid >> 1, nh = wid & 1;
            const int arow = mt*16 + g;
            const u32* w1h = wsw;                 // copy 0, [64][68] u32 rows
            const u32* w1l = wsw + 17408/4;       // copy 1
            float hacc[4][4];
            #pragma unroll
            for (int nt = 0; nt < 4; nt++)
                #pragma unroll
                for (int e = 0; e < 4; e++) hacc[nt][e] = 0.f;
            #pragma unroll 1
            for (int ks = 0; ks < 8; ks++) {
                int base0 = arow*68 + ks*8 + t;
                int base1 = base0 + 8*68;
                u32 ah0 = fhw[base0], ah1 = fhw[base1], ah2 = fhw[base0+4], ah3 = fhw[base1+4];
                u32 al0 = flw[base0], al1 = flw[base1], al2 = flw[base0+4], al3 = flw[base1+4];
                #pragma unroll
                for (int nt = 0; nt < 4; nt++) {
                    int bn = nh*32 + nt*8 + g;
                    int bidx = bn*68 + ks*8 + t;          // FIXED: W1^T row stride = 68 u32
                    u32 bh0 = w1h[bidx], bh1 = w1h[bidx+4];
                    u32 bl0 = w1l[bidx], bl1 = w1l[bidx+4];
                    mma16816(hacc[nt], ah0, ah1, ah2, ah3, bh0, bh1);
                    mma16816(hacc[nt], al0, al1, al2, al3, bh0, bh1);
                    mma16816(hacc[nt], ah0, ah1, ah2, ah3, bl0, bl1);
                }
            }
            // epilogue: +bias, relu, split -> hh/hl
            #pragma unroll
            for (int nt = 0; nt < 4; nt++) {
                int col = nh*32 + nt*8 + t2;
                float b0 = ob1[w*64 + col], b1v = ob1[w*64 + col + 1];
                float v0 = hacc[nt][0] + b0, v1 = hacc[nt][1] + b1v;
                float v2 = hacc[nt][2] + b0, v3 = hacc[nt][3] + b1v;
                v0 = v0 > 0.f ? v0 : 0.f; v1 = v1 > 0.f ? v1 : 0.f;
                v2 = v2 > 0.f ? v2 : 0.f; v3 = v3 > 0.f ? v3 : 0.f;
                u32 hp, lp;
                int cw = col/2;
                split2(v0, v1, hp, lp);
                hhw[arow*36 + cw] = hp; hlw[arow*36 + cw] = lp;
                split2(v2, v3, hp, lp);
                hhw[(arow+8)*36 + cw] = hp; hlw[(arow+8)*36 + cw] = lp;
            }
        }
        __syncthreads();

        // stage W2^T hi/lo: [copy][128][72] bf16
        {
            #pragma unroll
            for (int i = 0; i < 8; i++) {
                int idx = tid + i*256;
                int c = idx >> 10, e = idx & 1023;
                int n = e >> 3, c8 = e & 7;
                float4 v = *(const float4*)(&g_ow2t[w][c][n*64 + c8*8]);
                *(float4*)(smc + OFF_WS + c*18432 + (n*72 + c8*8)*2) = v;
            }
        }
        __syncthreads();

        // ---- tok = h @ W2 + b2 via mma: warps 4m x 2n(64) ----
        {
            const int mt = wid >> 1, nh = wid & 1;
            const int arow = mt*16 + g;
            const u32* w2h = wsw;
            const u32* w2l = wsw + 18432/4;
            float tacc[8][4];
            #pragma unroll
            for (int nt = 0; nt < 8; nt++)
                #pragma unroll
                for (int e = 0; e < 4; e++) tacc[nt][e] = 0.f;
            #pragma unroll 1
            for (int ks = 0; ks < 4; ks++) {
                int base0 = arow*36 + ks*8 + t;
                int base1 = base0 + 8*36;
                u32 ah0 = hhw[base0], ah1 = hhw[base1], ah2 = hhw[base0+4], ah3 = hhw[base1+4];
                u32 al0 = hlw[base0], al1 = hlw[base1], al2 = hlw[base0+4], al3 = hlw[base1+4];
                #pragma unroll
                for (int nt = 0; nt < 8; nt++) {
                    int bn = nh*64 + nt*8 + g;
                    int bidx = bn*36 + ks*8 + t;
                    u32 bh0 = w2h[bidx], bh1 = w2h[bidx+4];
                    u32 bl0 = w2l[bidx], bl1 = w2l[bidx+4];
                    mma16816(tacc[nt], ah0, ah1, ah2, ah3, bh0, bh1);
                    mma16816(tacc[nt], al0, al1, al2, al3, bh0, bh1);
                    mma16816(tacc[nt], ah0, ah1, ah2, ah3, bl0, bl1);
                }
            }
            // epilogue: +bias, split -> tokh/tokl
            #pragma unroll
            for (int nt = 0; nt < 8; nt++) {
                int col = nh*64 + nt*8 + t2;
                float b0 = ob2[w*128 + col], b1v = ob2[w*128 + col + 1];
                float v0 = tacc[nt][0] + b0, v1 = tacc[nt][1] + b1v;
                float v2 = tacc[nt][2] + b0, v3 = tacc[nt][3] + b1v;
                u32 hp, lp;
                int cw = col/2;
                split2(v0, v1, hp, lp);
                tokhw[arow*68 + cw] = hp; toklw[arow*68 + cw] = lp;
                split2(v2, v3, hp, lp);
                tokhw[(arow+8)*68 + cw] = hp; toklw[(arow+8)*68 + cw] = lp;
            }
        }
        __syncthreads();

        // ---- hid += tok @ fW1_k via mma (3-term), staged per (kc, copy) ----
        #pragma unroll 1
        for (int kc = 0; kc < 2; kc++) {
            #pragma unroll 1
            for (int copy = 0; copy < 2; copy++) {
                // stage bm [256 n][72 k] bf16
                {
                    const __nv_bfloat16* src = &g_fw1t[k][copy][0] + kc*64;
                    __nv_bfloat16* bmp = (__nv_bfloat16*)(smc + OFF_WS);
                    #pragma unroll
                    for (int i = 0; i < 8; i++) {
                        int idx = tid + i*256;
                        int n = idx >> 3, c8 = idx & 7;
                        float4 v = *(const float4*)(src + n*128 + c8*8);
                        *(float4*)(bmp + n*72 + c8*8) = v;
                    }
                }
                __syncthreads();
                #pragma unroll 1
                for (int ks = 0; ks < 4; ks++) {
                    int koff = kc*32 + ks*8 + t;
                    u32 ah[2][4], al[2][4];
                    #pragma unroll
                    for (int mt2 = 0; mt2 < 2; mt2++) {
                        int row = mh*32 + mt2*16 + g;
                        int base0 = row*68 + koff;
                        int base1 = base0 + 8*68;
                        ah[mt2][0] = tokhw[base0]; ah[mt2][1] = tokhw[base1];
                        ah[mt2][2] = tokhw[base0+4]; ah[mt2][3] = tokhw[base1+4];
                        if (copy == 0) {
                            al[mt2][0] = toklw[base0]; al[mt2][1] = toklw[base1];
                            al[mt2][2] = toklw[base0+4]; al[mt2][3] = toklw[base1+4];
                        }
                    }
                    #pragma unroll
                    for (int nt = 0; nt < 8; nt++) {
                        int bn = nq*64 + nt*8 + g;
                        int bidx = bn*36 + ks*8 + t;
                        u32 b0 = wsw[bidx], b1 = wsw[bidx+4];
                        #pragma unroll
                        for (int mt2 = 0; mt2 < 2; mt2++) {
                            mma16816(acc[mt2][nt], ah[mt2][0], ah[mt2][1], ah[mt2][2], ah[mt2][3], b0, b1);
                            if (copy == 0)
                                mma16816(acc[mt2][nt], al[mt2][0], al[mt2][1], al[mt2][2], al[mt2][3], b0, b1);
                        }
                    }
                }
                __syncthreads();
            }
        }
    }

    // ---- relu(acc) -> hid fp32 [64][260] (alias over xs+fh+fl) ----
    float* hid = (float*)(smc + OFF_HID);
    __syncthreads();
    #pragma unroll
    for (int mt2 = 0; mt2 < 2; mt2++) {
        int row = mh*32 + mt2*16 + g;
        #pragma unroll
        for (int nt = 0; nt < 8; nt++) {
            int q = nq*64 + nt*8 + t2;
            float2 v0, v1;
            v0.x = acc[mt2][nt][0] > 0.f ? acc[mt2][nt][0] : 0.f;
            v0.y = acc[mt2][nt][1] > 0.f ? acc[mt2][nt][1] : 0.f;
            v1.x = acc[mt2][nt][2] > 0.f ? acc[mt2][nt][2] : 0.f;
            v1.y = acc[mt2][nt][3] > 0.f ? acc[mt2][nt][3] : 0.f;
            *(float2*)(hid + row*260 + q)     = v0;
            *(float2*)(hid + (row+8)*260 + q) = v1;
        }
    }
    __syncthreads();

    // ---- fusion2 (scalar): out = relu(hid) @ fus_W2 + fus_b2 ----
    {
        float* wb = (float*)(smc + OFF_WS);
        const int dg = tid & 7, p2 = (tid >> 3) * 2;
        u64 oacc[2][4][2];
        #pragma unroll
        for (int qt = 0; qt < 4; qt++) {
            int d0 = qt*32 + dg*4;
            u64 b01 = pk2(fb2[d0],   fb2[d0+1]);
            u64 b23 = pk2(fb2[d0+2], fb2[d0+3]);
            oacc[0][qt][0] = b01; oacc[0][qt][1] = b23;
            oacc[1][qt][0] = b01; oacc[1][qt][1] = b23;
        }
        #pragma unroll 1
        for (int ch = 0; ch < 4; ch++) {
            {
                const float4* src = (const float4*)(fW2 + (size_t)ch * 64 * 128);
                float4* dst = (float4*)wb;
                #pragma unroll
                for (int i = 0; i < 8; i++) dst[tid + i*256] = src[tid + i*256];
            }
            __syncthreads();
            #pragma unroll 1
            for (int qq = 0; qq < 64; qq += 4) {
                float4 h0 = *(const float4*)(hid + p2*260 + ch*64 + qq);
                float4 h1 = *(const float4*)(hid + (p2+1)*260 + ch*64 + qq);
                #pragma unroll
                for (int e = 0; e < 4; e++) {
                    u64 u0 = dup2((&h0.x)[e]);
                    u64 u1 = dup2((&h1.x)[e]);
                    #pragma unroll
                    for (int qt = 0; qt < 4; qt++) {
                        ulonglong2 wv = *(const ulonglong2*)(wb + (qq+e)*128 + qt*32 + dg*4);
                        fma2(oacc[0][qt][0], u0, wv.x);
                        fma2(oacc[0][qt][1], u0, wv.y);
                        fma2(oacc[1][qt][0], u1, wv.x);
                        fma2(oacc[1][qt][1], u1, wv.y);
                    }
                }
            }
            __syncthreads();
        }
        #pragma unroll
        for (int i = 0; i < 2; i++) {
            int p = p2 + i;
            if (p0 + p < Pp) {
                float* orow = out + ((size_t)(b*Pp + p0 + p)) * 128;
                #pragma unroll
                for (int qt = 0; qt < 4; qt++) {
                    float4 v;
                    up2(oacc[i][qt][0], v.x, v.y);
                    up2(oacc[i][qt][1], v.z, v.w);
                    *(float4*)(orow + qt*32 + dg*4) = v;
                }
            }
        }
    }
}

extern "C" void kernel_launch(void* const* d_in, const int* in_sizes, int n_in,
                              void* d_out, int out_size) {
    const float* x        = (const float*)d_in[0];
    const int*   presence = (const int*)d_in[1];
    const int*   idx_i    = (const int*)d_in[2];
    const int*   idx_j    = (const int*)d_in[3];
    const float* oW1      = (const float*)d_in[4];
    const float* ob1      = (const float*)d_in[5];
    const float* oW2      = (const float*)d_in[6];
    const float* ob2      = (const float*)d_in[7];
    const float* pW1      = (const float*)d_in[8];
    const float* pb1      = (const float*)d_in[9];
    const float* pW2      = (const float*)d_in[10];
    const float* pb2      = (const float*)d_in[11];
    const float* fW1      = (const float*)d_in[12];
    const float* fb1      = (const float*)d_in[13];
    const float* fW2      = (const float*)d_in[14];
    const float* fb2      = (const float*)d_in[15];

    conv_kernel<<<1024, 256>>>(fW1, oW1, oW2);

    cudaFuncSetAttribute(dre_kernel, cudaFuncAttributeMaxDynamicSharedMemorySize, SMEM_BYTES);
    dre_kernel<<<2048, 256, SMEM_BYTES>>>(x, presence, idx_i, idx_j,
                                          oW1, ob1, oW2, ob2,
                                          pW1, pb1, pW2, pb2,
                                          fW1, fb1, fW2, fb2,
                                          (float*)d_out);
}

// round 10
// speedup vs baseline: 1.8302x; 1.1308x over previous
#include <cuda_runtime.h>
#include <cuda_bf16.h>
#include <cstdint>

// DynamicRelationshipExtractor — GB300 sm_103a, round 10
// = round 9 + (a) cp.async-pipelined weight staging (all stages hidden
//   behind compute, 12->7 syncs/phase), (b) fusion2 on mma.sync too
//   (hid stays in bf16 hi/lo panels, no fp32 roundtrip).

#define EPSF 1e-6f

static const int NC = 64;
static const int Dd = 128;
static const int Pp = 2016;
static const int TP = 64;

typedef unsigned long long u64;
typedef unsigned int u32;

__device__ __forceinline__ void mma16816(float* c, u32 a0, u32 a1, u32 a2, u32 a3,
                                         u32 b0, u32 b1) {
    asm volatile(
        "mma.sync.aligned.m16n8k16.row.col.f32.bf16.bf16.f32 "
        "{%0,%1,%2,%3},{%4,%5,%6,%7},{%8,%9},{%0,%1,%2,%3};"
        : "+f"(c[0]), "+f"(c[1]), "+f"(c[2]), "+f"(c[3])
        : "r"(a0), "r"(a1), "r"(a2), "r"(a3), "r"(b0), "r"(b1));
}

__device__ __forceinline__ void split2(float a, float b, u32 &hp, u32 &lp) {
    __nv_bfloat16 ha = __float2bfloat16(a), hb_ = __float2bfloat16(b);
    __nv_bfloat16 la = __float2bfloat16(a - __bfloat162float(ha));
    __nv_bfloat16 lb = __float2bfloat16(b - __bfloat162float(hb_));
    hp = ((u32)__bfloat16_as_ushort(hb_) << 16) | (u32)__bfloat16_as_ushort(ha);
    lp = ((u32)__bfloat16_as_ushort(lb)  << 16) | (u32)__bfloat16_as_ushort(la);
}

__device__ __forceinline__ u32 smem_u32(const void* p) {
    u32 a; asm("{ .reg .u64 t; cvta.to.shared.u64 t, %1; cvt.u32.u64 %0, t; }" : "=r"(a) : "l"(p));
    return a;
}
__device__ __forceinline__ void cpa16(u32 dst, const void* src) {
    asm volatile("cp.async.cg.shared.global [%0], [%1], 16;"
                 :: "r"(dst), "l"(__cvta_generic_to_global(src)));
}
#define CPA_COMMIT() asm volatile("cp.async.commit_group;" ::: "memory")
#define CPA_WAIT0()  asm volatile("cp.async.wait_group 0;" ::: "memory")

// precomputed weight images (bf16 hi/lo, B-operand [n][k] layouts)
__device__ __align__(16) __nv_bfloat16 g_fw1t[8][2][32768]; // fW1^T [kp]: [256 n][128 k]
__device__ __align__(16) __nv_bfloat16 g_ow1t[6][2][8192];  // W1^T:  [64 n(j)][128 k(d)]
__device__ __align__(16) __nv_bfloat16 g_ow2t[6][2][8192];  // W2^T:  [128 n(d)][64 k(j)]
__device__ __align__(16) __nv_bfloat16 g_fw2t[2][32768];    // fW2^T: [128 n(d)][256 k(q)]

__global__ void conv_kernel(const float* __restrict__ fW1,
                            const float* __restrict__ oW1,
                            const float* __restrict__ oW2,
                            const float* __restrict__ fW2) {
    int idx = blockIdx.x * blockDim.x + threadIdx.x;   // 0..262143
    {
        int kp = idx >> 15;
        int e  = idx & 32767;
        int n  = e >> 7, kk = e & 127;
        float v = fW1[(size_t)(kp*128 + kk) * 256 + n];
        __nv_bfloat16 hi = __float2bfloat16(v);
        __nv_bfloat16 lo = __float2bfloat16(v - __bfloat162float(hi));
        g_fw1t[kp][0][n*128 + kk] = hi;
        g_fw1t[kp][1][n*128 + kk] = lo;
    }
    if (idx < 49152) {
        int w = idx >> 13;
        int e = idx & 8191;
        {
            int n = e >> 7, kk = e & 127;       // n=j, k=d
            float v = oW1[(size_t)w*8192 + kk*64 + n];
            __nv_bfloat16 hi = __float2bfloat16(v);
            __nv_bfloat16 lo = __float2bfloat16(v - __bfloat162float(hi));
            g_ow1t[w][0][n*128 + kk] = hi;
            g_ow1t[w][1][n*128 + kk] = lo;
        }
        {
            int n = e >> 6, kk = e & 63;        // n=d, k=j
            float v = oW2[(size_t)w*8192 + kk*128 + n];
            __nv_bfloat16 hi = __float2bfloat16(v);
            __nv_bfloat16 lo = __float2bfloat16(v - __bfloat162float(hi));
            g_ow2t[w][0][n*64 + kk] = hi;
            g_ow2t[w][1][n*64 + kk] = lo;
        }
    }
    if (idx < 32768) {
        int n = idx >> 8, kk = idx & 255;       // n=d(128), k=q(256)
        float v = fW2[(size_t)kk*128 + n];
        __nv_bfloat16 hi = __float2bfloat16(v);
        __nv_bfloat16 lo = __float2bfloat16(v - __bfloat162float(hi));
        g_fw2t[0][n*256 + kk] = hi;
        g_fw2t[1][n*256 + kk] = lo;
    }
}

// ---- shared layout (BYTE offsets) ----
#define OFF_XS     0          // 32768 (fp32 x[b])
#define OFF_FH     32768      // [64][136] bf16 = 17408
#define OFF_FL     50176      // 17408 -> 67584
#define OFF_HH     67584      // [64][72] bf16 = 9216
#define OFF_HL     76800      // 9216 -> 86016
#define OFF_TOKH   86016      // [64][136] = 17408
#define OFF_TOKL   103424     // 17408 -> 120832
#define OFF_WS0    120832     // 36864 ping
#define OFF_WS1    157696     // 36864 pong -> 194560
#define OFF_PCON   194560     // 1024 fl
#define OFF_PTOK4  198656     // 512 fl
#define OFF_PH4    200704     // 256 fl
#define OFF_INORM  201728     // 64 fl
#define OFF_INTS   201984     // 3*64 int
#define SMEM_BYTES 202752
// hid bf16 panels alias [0, 67584): hi [64][264] at 0, lo at 33792
#define OFF_HIDH   0
#define OFF_HIDL   33792

__device__ __forceinline__ float featf(int k, float a, float c, float ni, float nj) {
    switch (k) {
        case 0: return a * c;
        case 1: return a + c;
        case 2: return (a * ni) * (c * nj);
        case 3: return fabsf(a - c);
        case 4: return a - c;
        case 5: return c - a;
        case 6: return __fdiv_rn(a, c + EPSF);
        default: return __fdiv_rn(c, a + EPSF);
    }
}

__global__ void __launch_bounds__(256, 1)
dre_kernel(const float* __restrict__ x, const int* __restrict__ presence,
           const int* __restrict__ idx_i, const int* __restrict__ idx_j,
           const float* __restrict__ oW1, const float* __restrict__ ob1,
           const float* __restrict__ oW2, const float* __restrict__ ob2,
           const float* __restrict__ pW1, const float* __restrict__ pb1,
           const float* __restrict__ pW2, const float* __restrict__ pb2,
           const float* __restrict__ fW1, const float* __restrict__ fb1,
           const float* __restrict__ fW2, const float* __restrict__ fb2,
           float* __restrict__ out)
{
    extern __shared__ float sm[];
    char*  smc   = (char*)sm;
    float* xs    = (float*)(smc + OFF_XS);
    u32*   fhw   = (u32*)(smc + OFF_FH);
    u32*   flw   = (u32*)(smc + OFF_FL);
    u32*   hhw   = (u32*)(smc + OFF_HH);
    u32*   hlw   = (u32*)(smc + OFF_HL);
    u32*   tokhw = (u32*)(smc + OFF_TOKH);
    u32*   toklw = (u32*)(smc + OFF_TOKL);
    u32*   ws0w  = (u32*)(smc + OFF_WS0);
    u32*   ws1w  = (u32*)(smc + OFF_WS1);
    float* pcon  = (float*)(smc + OFF_PCON);
    float* ptok4 = (float*)(smc + OFF_PTOK4);
    float* ph4   = (float*)(smc + OFF_PH4);
    float* inorm = (float*)(smc + OFF_INORM);
    int*   pi    = (int*)(smc + OFF_INTS);
    int*   pj    = pi + 64;
    int*   pcx   = pj + 64;

    const int tid = threadIdx.x;
    const int b   = blockIdx.x >> 5;
    const int p0  = (blockIdx.x & 31) * TP;
    const int wid = tid >> 5, lane = tid & 31;
    const int g   = lane >> 2;          // frag row group 0..7
    const int t   = lane & 3;           // frag k-word 0..3
    const int t2  = t * 2;
    const u32 sb  = smem_u32(sm);

    // ---- load x[b] ----
    {
        const float4* src = (const float4*)(x + (size_t)b * NC * Dd);
        float4* dst = (float4*)xs;
        #pragma unroll
        for (int i = 0; i < 8; i++) dst[tid + i*256] = src[tid + i*256];
    }
    if (tid < TP) {
        int pp = p0 + tid; if (pp >= Pp) pp = Pp - 1;
        int ii = idx_i[pp], jj = idx_j[pp];
        pi[tid] = ii; pj[tid] = jj;
        int pa = presence[b*NC + ii], pb_ = presence[b*NC + jj];
        pcx[tid] = pa ? (pb_ ? 0 : 1) : (pb_ ? 2 : 3);
    }
    {
        int c = tid >> 6, tt = tid & 63;
        float v = pW1[c*64 + tt] + pb1[tt];
        ph4[tid] = v > 0.f ? v : 0.f;
    }
    __syncthreads();

    if (tid < NC) {
        float s = 0.f;
        const float* row = xs + tid * Dd;
        #pragma unroll 8
        for (int d = 0; d < Dd; d++) { float v = row[d]; s = fmaf(v, v, s); }
        inorm[tid] = __fdiv_rn(1.f, __fsqrt_rn(s) + EPSF);
    }
    for (int o = tid; o < 512; o += 256) {
        int c = o >> 7, d = o & 127;
        float s = pb2[d];
        const float* ph = ph4 + c*64;
        #pragma unroll 8
        for (int tt = 0; tt < 64; tt++) s = fmaf(ph[tt], pW2[tt*128 + d], s);
        ptok4[o] = s;
    }
    __syncthreads();
    for (int o = tid; o < 1024; o += 256) {
        int c = o >> 8, q = o & 255;
        float s = 0.f;
        const float* pt = ptok4 + c*128;
        #pragma unroll 8
        for (int d = 0; d < 128; d++) s = fmaf(pt[d], fW1[(size_t)(1024 + d)*256 + q], s);
        pcon[o] = s;
    }
    __syncthreads();

    // ---- hid accumulator fragments: warps 2m x 4n ----
    const int mh = wid & 1;        // rows mh*32 .. +31
    const int nq = wid >> 1;       // cols nq*64 .. +63
    float acc[2][8][4];
    #pragma unroll
    for (int mt2 = 0; mt2 < 2; mt2++) {
        int row = mh*32 + mt2*16 + g;
        int c0 = pcx[row], c1 = pcx[row + 8];
        #pragma unroll
        for (int nt = 0; nt < 8; nt++) {
            int q = nq*64 + nt*8 + t2;
            acc[mt2][nt][0] = fb1[q]   + pcon[c0*256 + q];
            acc[mt2][nt][1] = fb1[q+1] + pcon[c0*256 + q + 1];
            acc[mt2][nt][2] = fb1[q]   + pcon[c1*256 + q];
            acc[mt2][nt][3] = fb1[q+1] + pcon[c1*256 + q + 1];
        }
    }

    const int mlp_idx[8] = {0, 1, 2, 3, 4, 4, 5, 5};

    #pragma unroll 1
    for (int k = 0; k < 8; k++) {
        const int w = mlp_idx[k];

        // ---- S1: cp.async W1->WS0 [copy][64][136], W2->WS1 [copy][128][72]; feats ----
        #pragma unroll
        for (int i = 0; i < 8; i++) {
            int idx = tid + i*256;              // 0..2047
            int c = idx >> 10, e = idx & 1023;
            int n = e >> 4, c8 = e & 15;
            cpa16(sb + OFF_WS0 + c*17408 + n*272 + c8*16, &g_ow1t[w][c][n*128 + c8*8]);
        }
        #pragma unroll
        for (int i = 0; i < 8; i++) {
            int idx = tid + i*256;
            int c = idx >> 10, e = idx & 1023;
            int n = e >> 3, c8 = e & 7;
            cpa16(sb + OFF_WS1 + c*18432 + n*144 + c8*16, &g_ow2t[w][c][n*64 + c8*8]);
        }
        CPA_COMMIT();

        #pragma unroll 1
        for (int it = 0; it < 8; it++) {
            int o = tid + it*256;
            int p = o >> 5, d4 = (o & 31) * 4;
            int ci = pi[p], cj = pj[p];
            float4 a4 = *(const float4*)(xs + ci*Dd + d4);
            float4 c4 = *(const float4*)(xs + cj*Dd + d4);
            float ni = inorm[ci], nj = inorm[cj];
            float f0 = featf(k, a4.x, c4.x, ni, nj);
            float f1 = featf(k, a4.y, c4.y, ni, nj);
            float f2 = featf(k, a4.z, c4.z, ni, nj);
            float f3 = featf(k, a4.w, c4.w, ni, nj);
            u32 h01, l01, h23, l23;
            split2(f0, f1, h01, l01);
            split2(f2, f3, h23, l23);
            int widx = p*68 + d4/2;
            *(uint2*)(fhw + widx) = make_uint2(h01, h23);
            *(uint2*)(flw + widx) = make_uint2(l01, l23);
        }
        CPA_WAIT0();
        __syncthreads();

        // ---- S2: h = relu(feats @ W1 + b1): warps 4m x 2n(32) ----
        {
            const int mt = wid >> 1, nh = wid & 1;
            const int arow = mt*16 + g;
            const u32* w1h = ws0w;                // [64][68] u32 rows
            const u32* w1l = ws0w + 4352;         // +17408B
            float hacc[4][4];
            #pragma unroll
            for (int nt = 0; nt < 4; nt++)
                #pragma unroll
                for (int e = 0; e < 4; e++) hacc[nt][e] = 0.f;
            #pragma unroll 1
            for (int ks = 0; ks < 8; ks++) {
                int base0 = arow*68 + ks*8 + t;
                int base1 = base0 + 8*68;
                u32 ah0 = fhw[base0], ah1 = fhw[base1], ah2 = fhw[base0+4], ah3 = fhw[base1+4];
                u32 al0 = flw[base0], al1 = flw[base1], al2 = flw[base0+4], al3 = flw[base1+4];
                #pragma unroll
                for (int nt = 0; nt < 4; nt++) {
                    int bn = nh*32 + nt*8 + g;
                    int bidx = bn*68 + ks*8 + t;
                    u32 bh0 = w1h[bidx], bh1 = w1h[bidx+4];
                    u32 bl0 = w1l[bidx], bl1 = w1l[bidx+4];
                    mma16816(hacc[nt], ah0, ah1, ah2, ah3, bh0, bh1);
                    mma16816(hacc[nt], al0, al1, al2, al3, bh0, bh1);
                    mma16816(hacc[nt], ah0, ah1, ah2, ah3, bl0, bl1);
                }
            }
            #pragma unroll
            for (int nt = 0; nt < 4; nt++) {
                int col = nh*32 + nt*8 + t2;
                float b0 = ob1[w*64 + col], b1v = ob1[w*64 + col + 1];
                float v0 = hacc[nt][0] + b0, v1 = hacc[nt][1] + b1v;
                float v2 = hacc[nt][2] + b0, v3 = hacc[nt][3] + b1v;
                v0 = v0 > 0.f ? v0 : 0.f; v1 = v1 > 0.f ? v1 : 0.f;
                v2 = v2 > 0.f ? v2 : 0.f; v3 = v3 > 0.f ? v3 : 0.f;
                u32 hp, lp;
                int cw = col/2;
                split2(v0, v1, hp, lp);
                hhw[arow*36 + cw] = hp; hlw[arow*36 + cw] = lp;
                split2(v2, v3, hp, lp);
                hhw[(arow+8)*36 + cw] = hp; hlw[(arow+8)*36 + cw] = lp;
            }
        }
        __syncthreads();

        // ---- S3: issue u0 = fW1[k][hi] kc0 -> WS0; tok = h @ W2 + b2 (B=WS1) ----
        #pragma unroll
        for (int i = 0; i < 8; i++) {
            int idx = tid + i*256;
            int n = idx >> 3, c8 = idx & 7;
            cpa16(sb + OFF_WS0 + n*144 + c8*16, &g_fw1t[k][0][n*128 + c8*8]);
        }
        CPA_COMMIT();
        {
            const int mt = wid >> 1, nh = wid & 1;
            const int arow = mt*16 + g;
            const u32* w2h = ws1w;
            const u32* w2l = ws1w + 4608;         // +18432B
            float tacc[8][4];
            #pragma unroll
            for (int nt = 0; nt < 8; nt++)
                #pragma unroll
                for (int e = 0; e < 4; e++) tacc[nt][e] = 0.f;
            #pragma unroll 1
            for (int ks = 0; ks < 4; ks++) {
                int base0 = arow*36 + ks*8 + t;
                int base1 = base0 + 8*36;
                u32 ah0 = hhw[base0], ah1 = hhw[base1], ah2 = hhw[base0+4], ah3 = hhw[base1+4];
                u32 al0 = hlw[base0], al1 = hlw[base1], al2 = hlw[base0+4], al3 = hlw[base1+4];
                #pragma unroll
                for (int nt = 0; nt < 8; nt++) {
                    int bn = nh*64 + nt*8 + g;
                    int bidx = bn*36 + ks*8 + t;
                    u32 bh0 = w2h[bidx], bh1 = w2h[bidx+4];
                    u32 bl0 = w2l[bidx], bl1 = w2l[bidx+4];
                    mma16816(tacc[nt], ah0, ah1, ah2, ah3, bh0, bh1);
                    mma16816(tacc[nt], al0, al1, al2, al3, bh0, bh1);
                    mma16816(tacc[nt], ah0, ah1, ah2, ah3, bl0, bl1);
                }
            }
            #pragma unroll
            for (int nt = 0; nt < 8; nt++) {
                int col = nh*64 + nt*8 + t2;
                float b0 = ob2[w*128 + col], b1v = ob2[w*128 + col + 1];
                float v0 = tacc[nt][0] + b0, v1 = tacc[nt][1] + b1v;
                float v2 = tacc[nt][2] + b0, v3 = tacc[nt][3] + b1v;
                u32 hp, lp;
                int cw = col/2;
                split2(v0, v1, hp, lp);
                tokhw[arow*68 + cw] = hp; toklw[arow*68 + cw] = lp;
                split2(v2, v3, hp, lp);
                tokhw[(arow+8)*68 + cw] = hp; toklw[(arow+8)*68 + cw] = lp;
            }
        }
        CPA_WAIT0();
        __syncthreads();

        // ---- hid-update: 4 pipelined sub-stages ----
        #pragma unroll 1
        for (int u = 0; u < 4; u++) {
            // issue next sub-stage while doing mma on current
            // u=0: mma hi kc0 (WS0), issue lo kc0 -> WS1
            // u=1: mma lo kc0 (WS1), issue hi kc1 -> WS0
            // u=2: mma hi kc1 (WS0), issue lo kc1 -> WS1
            // u=3: mma lo kc1 (WS1)
            if (u < 3) {
                int nc_copy = (u == 1) ? 0 : 1;          // which image copy to fetch next
                int nc_kc   = (u == 0) ? 0 : 1;
                u32 dstb = (u == 1) ? (sb + OFF_WS0) : (sb + OFF_WS1);
                const __nv_bfloat16* src = &g_fw1t[k][nc_copy][0] + nc_kc*64;
                #pragma unroll
                for (int i = 0; i < 8; i++) {
                    int idx = tid + i*256;
                    int n = idx >> 3, c8 = idx & 7;
                    cpa16(dstb + n*144 + c8*16, src + n*128 + c8*8);
                }
                CPA_COMMIT();
            }
            const int kc = u >> 1;
            const int hiterm = ((u & 1) == 0);
            const u32* bp = (u == 0 || u == 2) ? ws0w : ws1w;
            #pragma unroll 1
            for (int ks = 0; ks < 4; ks++) {
                int koff = kc*32 + ks*8 + t;
                u32 ah[2][4], al[2][4];
                #pragma unroll
                for (int mt2 = 0; mt2 < 2; mt2++) {
                    int row = mh*32 + mt2*16 + g;
                    int base0 = row*68 + koff;
                    int base1 = base0 + 8*68;
                    ah[mt2][0] = tokhw[base0]; ah[mt2][1] = tokhw[base1];
                    ah[mt2][2] = tokhw[base0+4]; ah[mt2][3] = tokhw[base1+4];
                    if (hiterm) {
                        al[mt2][0] = toklw[base0]; al[mt2][1] = toklw[base1];
                        al[mt2][2] = toklw[base0+4]; al[mt2][3] = toklw[base1+4];
                    }
                }
                #pragma unroll
                for (int nt = 0; nt < 8; nt++) {
                    int bn = nq*64 + nt*8 + g;
                    int bidx = bn*36 + ks*8 + t;
                    u32 b0 = bp[bidx], b1 = bp[bidx+4];
                    #pragma unroll
                    for (int mt2 = 0; mt2 < 2; mt2++) {
                        mma16816(acc[mt2][nt], ah[mt2][0], ah[mt2][1], ah[mt2][2], ah[mt2][3], b0, b1);
                        if (hiterm)
                            mma16816(acc[mt2][nt], al[mt2][0], al[mt2][1], al[mt2][2], al[mt2][3], b0, b1);
                    }
                }
            }
            if (u < 3) CPA_WAIT0();
            __syncthreads();
        }
    }

    // ---- F1: hid epilogue -> bf16 hi/lo panels [64][264]; stage fW2 kc0 ----
    u32* hidh = (u32*)(smc + OFF_HIDH);   // stride 132 u32
    u32* hidl = (u32*)(smc + OFF_HIDL);
    #pragma unroll
    for (int i = 0; i < 8; i++) {         // fW2 kc0: hi->WS0, lo->WS1, [128][136] panels
        int idx = tid + i*256;
        int n = idx >> 4, c8 = idx & 15;
        cpa16(sb + OFF_WS0 + n*272 + c8*16, &g_fw2t[0][n*256 + c8*8]);
        cpa16(sb + OFF_WS1 + n*272 + c8*16, &g_fw2t[1][n*256 + c8*8]);
    }
    CPA_COMMIT();
    #pragma unroll
    for (int mt2 = 0; mt2 < 2; mt2++) {
        #pragma unroll
        for (int nt = 0; nt < 8; nt++) {
            int row = mh*32 + mt2*16 + g;
            float v0 = acc[mt2][nt][0] > 0.f ? acc[mt2][nt][0] : 0.f;
            float v1 = acc[mt2][nt][1] > 0.f ? acc[mt2][nt][1] : 0.f;
            float v2 = acc[mt2][nt][2] > 0.f ? acc[mt2][nt][2] : 0.f;
            float v3 = acc[mt2][nt][3] > 0.f ? acc[mt2][nt][3] : 0.f;
            int cw = nq*32 + nt*4 + t;
            u32 hp, lp;
            split2(v0, v1, hp, lp);
            hidh[row*132 + cw] = hp; hidl[row*132 + cw] = lp;
            split2(v2, v3, hp, lp);
            hidh[(row+8)*132 + cw] = hp; hidl[(row+8)*132 + cw] = lp;
        }
    }
    CPA_WAIT0();
    __syncthreads();

    // ---- F2..F4: out = relu(hid) @ fW2 + fb2 via mma: warps 4m x 2n(64) ----
    {
        const int mt = wid >> 1, nh = wid & 1;
        const int arow = mt*16 + g;
        float acc2[8][4];
        #pragma unroll
        for (int nt = 0; nt < 8; nt++)
            #pragma unroll
            for (int e = 0; e < 4; e++) acc2[nt][e] = 0.f;

        #pragma unroll 1
        for (int kc = 0; kc < 2; kc++) {
            if (kc == 1) {
                // stage kc1 (exposed; WS free after sync below)
                #pragma unroll
                for (int i = 0; i < 8; i++) {
                    int idx = tid + i*256;
                    int n = idx >> 4, c8 = idx & 15;
                    cpa16(sb + OFF_WS0 + n*272 + c8*16, &g_fw2t[0][n*256 + 128 + c8*8]);
                    cpa16(sb + OFF_WS1 + n*272 + c8*16, &g_fw2t[1][n*256 + 128 + c8*8]);
                }
                CPA_COMMIT();
                CPA_WAIT0();
                __syncthreads();
            }
            #pragma unroll 1
            for (int ks = 0; ks < 8; ks++) {
                int base0 = arow*132 + kc*64 + ks*8 + t;
                int base1 = base0 + 8*132;
                u32 ah0 = hidh[base0], ah1 = hidh[base1], ah2 = hidh[base0+4], ah3 = hidh[base1+4];
                u32 al0 = hidl[base0], al1 = hidl[base1], al2 = hidl[base0+4], al3 = hidl[base1+4];
                #pragma unroll
                for (int nt = 0; nt < 8; nt++) {
                    int bn = nh*64 + nt*8 + g;
                    int bidx = bn*68 + ks*8 + t;
                    u32 bh0 = ws0w[bidx], bh1 = ws0w[bidx+4];
                    u32 bl0 = ws1w[bidx], bl1 = ws1w[bidx+4];
                    mma16816(acc2[nt], ah0, ah1, ah2, ah3, bh0, bh1);
                    mma16816(acc2[nt], al0, al1, al2, al3, bh0, bh1);
                    mma16816(acc2[nt], ah0, ah1, ah2, ah3, bl0, bl1);
                }
            }
            if (kc == 0) __syncthreads();   // all warps done with kc0 panels
        }

        // epilogue: + fb2, store to gmem
        #pragma unroll
        for (int nt = 0; nt < 8; nt++) {
            int col = nh*64 + nt*8 + t2;
            float b0 = fb2[col], b1v = fb2[col + 1];
            int r0 = mt*16 + g, r1 = r0 + 8;
            if (p0 + r0 < Pp) {
                float2 v = make_float2(acc2[nt][0] + b0, acc2[nt][1] + b1v);
                *(float2*)(out + ((size_t)(b*Pp + p0 + r0))*128 + col) = v;
            }
            if (p0 + r1 < Pp) {
                float2 v = make_float2(acc2[nt][2] + b0, acc2[nt][3] + b1v);
                *(float2*)(out + ((size_t)(b*Pp + p0 + r1))*128 + col) = v;
            }
        }
    }
}

extern "C" void kernel_launch(void* const* d_in, const int* in_sizes, int n_in,
                              void* d_out, int out_size) {
    const float* x        = (const float*)d_in[0];
    const int*   presence = (const int*)d_in[1];
    const int*   idx_i    = (const int*)d_in[2];
    const int*   idx_j    = (const int*)d_in[3];
    const float* oW1      = (const float*)d_in[4];
    const float* ob1      = (const float*)d_in[5];
    const float* oW2      = (const float*)d_in[6];
    const float* ob2      = (const float*)d_in[7];
    const float* pW1      = (const float*)d_in[8];
    const float* pb1      = (const float*)d_in[9];
    const float* pW2      = (const float*)d_in[10];
    const float* pb2      = (const float*)d_in[11];
    const float* fW1      = (const float*)d_in[12];
    const float* fb1      = (const float*)d_in[13];
    const float* fW2      = (const float*)d_in[14];
    const float* fb2      = (const float*)d_in[15];

    conv_kernel<<<1024, 256>>>(fW1, oW1, oW2, fW2);

    cudaFuncSetAttribute(dre_kernel, cudaFuncAttributeMaxDynamicSharedMemorySize, SMEM_BYTES);
    dre_kernel<<<2048, 256, SMEM_BYTES>>>(x, presence, idx_i, idx_j,
                                          oW1, ob1, oW2, ob2,
                                          pW1, pb1, pW2, pb2,
                                          fW1, fb1, fW2, fb2,
                                          (float*)d_out);
}

// round 11
// speedup vs baseline: 3.0212x; 1.6508x over previous
#include <cuda_runtime.h>
#include <cuda_bf16.h>
#include <cstdint>

// DynamicRelationshipExtractor — GB300 sm_103a, round 11
// = round 10 + algebraic fusion: hid += tok@fW1 rewritten as h@(W2@fW1_k),
//   with G_k = W2@fW1_k and csum = sum_k b2@fW1_k precomputed in the prologue.
//   Deletes the tok GEMM, halves per-phase mma work, syncs 7->4 per phase.

#define EPSF 1e-6f

static const int NC = 64;
static const int Dd = 128;
static const int Pp = 2016;
static const int TP = 64;

typedef unsigned long long u64;
typedef unsigned int u32;

__device__ __forceinline__ void mma16816(float* c, u32 a0, u32 a1, u32 a2, u32 a3,
                                         u32 b0, u32 b1) {
    asm volatile(
        "mma.sync.aligned.m16n8k16.row.col.f32.bf16.bf16.f32 "
        "{%0,%1,%2,%3},{%4,%5,%6,%7},{%8,%9},{%0,%1,%2,%3};"
        : "+f"(c[0]), "+f"(c[1]), "+f"(c[2]), "+f"(c[3])
        : "r"(a0), "r"(a1), "r"(a2), "r"(a3), "r"(b0), "r"(b1));
}

__device__ __forceinline__ void split2(float a, float b, u32 &hp, u32 &lp) {
    __nv_bfloat16 ha = __float2bfloat16(a), hb_ = __float2bfloat16(b);
    __nv_bfloat16 la = __float2bfloat16(a - __bfloat162float(ha));
    __nv_bfloat16 lb = __float2bfloat16(b - __bfloat162float(hb_));
    hp = ((u32)__bfloat16_as_ushort(hb_) << 16) | (u32)__bfloat16_as_ushort(ha);
    lp = ((u32)__bfloat16_as_ushort(lb)  << 16) | (u32)__bfloat16_as_ushort(la);
}

__device__ __forceinline__ u32 smem_u32(const void* p) {
    u32 a; asm("{ .reg .u64 t; cvta.to.shared.u64 t, %1; cvt.u32.u64 %0, t; }" : "=r"(a) : "l"(p));
    return a;
}
__device__ __forceinline__ void cpa16(u32 dst, const void* src) {
    asm volatile("cp.async.cg.shared.global [%0], [%1], 16;"
                 :: "r"(dst), "l"(__cvta_generic_to_global(src)));
}
#define CPA_COMMIT() asm volatile("cp.async.commit_group;" ::: "memory")
#define CPA_WAIT0()  asm volatile("cp.async.wait_group 0;" ::: "memory")

// precomputed weight images (bf16 hi/lo, B-operand [n][k] layouts)
__device__ __align__(16) __nv_bfloat16 g_ow1t[6][2][8192];   // W1^T: [64 n(j)][128 k(d)]
__device__ __align__(16) __nv_bfloat16 g_gt[8][2][16384];    // G_k^T: [256 n(q)][64 k(j)]
__device__ __align__(16) __nv_bfloat16 g_fw2t[2][32768];     // fW2^T: [128 n(d)][256 k(q)]
__device__ float g_csum[256];                                 // sum_k b2@fW1_k

__global__ void conv_kernel(const float* __restrict__ fW1,
                            const float* __restrict__ oW1,
                            const float* __restrict__ oW2,
                            const float* __restrict__ ob2,
                            const float* __restrict__ fW2) {
    const int mlp_idx[8] = {0, 1, 2, 3, 4, 4, 5, 5};
    int idx = blockIdx.x * blockDim.x + threadIdx.x;   // 0..262143

    // G_k[j][q] = sum_d W2[w(k)][j][d] * fW1[k*128+d][q], stored ^T [q][j]
    if (idx < 131072) {
        int kidx = idx >> 14;
        int e = idx & 16383;
        int q = e & 255, j = e >> 8;
        int w = mlp_idx[kidx];
        const float* w2row = oW2 + (size_t)w*8192 + j*128;
        const float* f1col = fW1 + (size_t)kidx*128*256 + q;
        float s = 0.f;
        #pragma unroll 8
        for (int d = 0; d < 128; d++) s = fmaf(w2row[d], f1col[(size_t)d*256], s);
        __nv_bfloat16 hi = __float2bfloat16(s);
        __nv_bfloat16 lo = __float2bfloat16(s - __bfloat162float(hi));
        g_gt[kidx][0][q*64 + j] = hi;
        g_gt[kidx][1][q*64 + j] = lo;
    }
    if (idx < 49152) {
        int w = idx >> 13;
        int e = idx & 8191;
        int n = e >> 7, kk = e & 127;       // n=j, k=d
        float v = oW1[(size_t)w*8192 + kk*64 + n];
        __nv_bfloat16 hi = __float2bfloat16(v);
        __nv_bfloat16 lo = __float2bfloat16(v - __bfloat162float(hi));
        g_ow1t[w][0][n*128 + kk] = hi;
        g_ow1t[w][1][n*128 + kk] = lo;
    }
    if (idx < 32768) {
        int n = idx >> 8, kk = idx & 255;   // n=d(128), k=q(256)
        float v = fW2[(size_t)kk*128 + n];
        __nv_bfloat16 hi = __float2bfloat16(v);
        __nv_bfloat16 lo = __float2bfloat16(v - __bfloat162float(hi));
        g_fw2t[0][n*256 + kk] = hi;
        g_fw2t[1][n*256 + kk] = lo;
    }
    if (idx < 256) {
        int q = idx;
        float s = 0.f;
        for (int kk = 0; kk < 8; kk++) {
            int w = mlp_idx[kk];
            const float* b2r = ob2 + w*128;
            const float* f1c = fW1 + (size_t)kk*128*256 + q;
            #pragma unroll 8
            for (int d = 0; d < 128; d++) s = fmaf(b2r[d], f1c[(size_t)d*256], s);
        }
        g_csum[q] = s;
    }
}

// ---- shared layout (BYTE offsets) ----
#define OFF_XS     0          // 32768 (fp32 x[b])
#define OFF_FH     32768      // [64][136] bf16 = 17408
#define OFF_FL     50176      // 17408 -> 67584
#define OFF_HH     67584      // [64][72] bf16 = 9216
#define OFF_HL     76800      // 9216 -> 86016
#define OFF_WS0    86016      // 36864 ping -> 122880
#define OFF_WS1    122880     // 36864 pong -> 159744
#define OFF_PCON   159744     // 1024 fl -> 163840
#define OFF_PTOK4  163840     // 512 fl -> 165888
#define OFF_PH4    165888     // 256 fl -> 166912
#define OFF_INORM  166912     // 64 fl -> 167168
#define OFF_INTS   167168     // 3*64 int -> 167936
#define SMEM_BYTES 167936
// hid bf16 panels alias [0, 67584): hi [64][264] at 0, lo at 33792
#define OFF_HIDH   0
#define OFF_HIDL   33792

__device__ __forceinline__ float featf(int k, float a, float c, float ni, float nj) {
    switch (k) {
        case 0: return a * c;
        case 1: return a + c;
        case 2: return (a * ni) * (c * nj);
        case 3: return fabsf(a - c);
        case 4: return a - c;
        case 5: return c - a;
        case 6: return __fdiv_rn(a, c + EPSF);
        default: return __fdiv_rn(c, a + EPSF);
    }
}

__global__ void __launch_bounds__(256, 1)
dre_kernel(const float* __restrict__ x, const int* __restrict__ presence,
           const int* __restrict__ idx_i, const int* __restrict__ idx_j,
           const float* __restrict__ oW1, const float* __restrict__ ob1,
           const float* __restrict__ oW2, const float* __restrict__ ob2,
           const float* __restrict__ pW1, const float* __restrict__ pb1,
           const float* __restrict__ pW2, const float* __restrict__ pb2,
           const float* __restrict__ fW1, const float* __restrict__ fb1,
           const float* __restrict__ fW2, const float* __restrict__ fb2,
           float* __restrict__ out)
{
    extern __shared__ float sm[];
    char*  smc   = (char*)sm;
    float* xs    = (float*)(smc + OFF_XS);
    u32*   fhw   = (u32*)(smc + OFF_FH);
    u32*   flw   = (u32*)(smc + OFF_FL);
    u32*   hhw   = (u32*)(smc + OFF_HH);
    u32*   hlw   = (u32*)(smc + OFF_HL);
    u32*   ws0w  = (u32*)(smc + OFF_WS0);
    u32*   ws1w  = (u32*)(smc + OFF_WS1);
    float* pcon  = (float*)(smc + OFF_PCON);
    float* ptok4 = (float*)(smc + OFF_PTOK4);
    float* ph4   = (float*)(smc + OFF_PH4);
    float* inorm = (float*)(smc + OFF_INORM);
    int*   pi    = (int*)(smc + OFF_INTS);
    int*   pj    = pi + 64;
    int*   pcx   = pj + 64;

    const int tid = threadIdx.x;
    const int b   = blockIdx.x >> 5;
    const int p0  = (blockIdx.x & 31) * TP;
    const int wid = tid >> 5, lane = tid & 31;
    const int g   = lane >> 2;          // frag row group 0..7
    const int t   = lane & 3;           // frag k-word 0..3
    const int t2  = t * 2;
    const u32 sb  = smem_u32(sm);

    // ---- load x[b] ----
    {
        const float4* src = (const float4*)(x + (size_t)b * NC * Dd);
        float4* dst = (float4*)xs;
        #pragma unroll
        for (int i = 0; i < 8; i++) dst[tid + i*256] = src[tid + i*256];
    }
    if (tid < TP) {
        int pp = p0 + tid; if (pp >= Pp) pp = Pp - 1;
        int ii = idx_i[pp], jj = idx_j[pp];
        pi[tid] = ii; pj[tid] = jj;
        int pa = presence[b*NC + ii], pb_ = presence[b*NC + jj];
        pcx[tid] = pa ? (pb_ ? 0 : 1) : (pb_ ? 2 : 3);
    }
    {
        int c = tid >> 6, tt = tid & 63;
        float v = pW1[c*64 + tt] + pb1[tt];
        ph4[tid] = v > 0.f ? v : 0.f;
    }
    __syncthreads();

    if (tid < NC) {
        float s = 0.f;
        const float* row = xs + tid * Dd;
        #pragma unroll 8
        for (int d = 0; d < Dd; d++) { float v = row[d]; s = fmaf(v, v, s); }
        inorm[tid] = __fdiv_rn(1.f, __fsqrt_rn(s) + EPSF);
    }
    for (int o = tid; o < 512; o += 256) {
        int c = o >> 7, d = o & 127;
        float s = pb2[d];
        const float* ph = ph4 + c*64;
        #pragma unroll 8
        for (int tt = 0; tt < 64; tt++) s = fmaf(ph[tt], pW2[tt*128 + d], s);
        ptok4[o] = s;
    }
    __syncthreads();
    for (int o = tid; o < 1024; o += 256) {
        int c = o >> 8, q = o & 255;
        float s = 0.f;
        const float* pt = ptok4 + c*128;
        #pragma unroll 8
        for (int d = 0; d < 128; d++) s = fmaf(pt[d], fW1[(size_t)(1024 + d)*256 + q], s);
        pcon[o] = s;
    }
    __syncthreads();

    // ---- hid accumulator fragments: warps 2m x 4n ----
    const int mh = wid & 1;        // rows mh*32 .. +31
    const int nq = wid >> 1;       // cols nq*64 .. +63
    float acc[2][8][4];
    #pragma unroll
    for (int mt2 = 0; mt2 < 2; mt2++) {
        int row = mh*32 + mt2*16 + g;
        int c0 = pcx[row], c1 = pcx[row + 8];
        #pragma unroll
        for (int nt = 0; nt < 8; nt++) {
            int q = nq*64 + nt*8 + t2;
            float cs0 = g_csum[q], cs1 = g_csum[q+1];
            acc[mt2][nt][0] = fb1[q]   + pcon[c0*256 + q]     + cs0;
            acc[mt2][nt][1] = fb1[q+1] + pcon[c0*256 + q + 1] + cs1;
            acc[mt2][nt][2] = fb1[q]   + pcon[c1*256 + q]     + cs0;
            acc[mt2][nt][3] = fb1[q+1] + pcon[c1*256 + q + 1] + cs1;
        }
    }

    const int mlp_idx[8] = {0, 1, 2, 3, 4, 4, 5, 5};

    #pragma unroll 1
    for (int k = 0; k < 8; k++) {
        const int w = mlp_idx[k];

        // ---- S1: cp.async W1 -> WS0 [copy][64][136]; feats -> fh/fl ----
        #pragma unroll
        for (int i = 0; i < 8; i++) {
            int idx = tid + i*256;              // 0..2047
            int c = idx >> 10, e = idx & 1023;
            int n = e >> 4, c8 = e & 15;
            cpa16(sb + OFF_WS0 + c*17408 + n*272 + c8*16, &g_ow1t[w][c][n*128 + c8*8]);
        }
        CPA_COMMIT();

        #pragma unroll 1
        for (int it = 0; it < 8; it++) {
            int o = tid + it*256;
            int p = o >> 5, d4 = (o & 31) * 4;
            int ci = pi[p], cj = pj[p];
            float4 a4 = *(const float4*)(xs + ci*Dd + d4);
            float4 c4 = *(const float4*)(xs + cj*Dd + d4);
            float ni = inorm[ci], nj = inorm[cj];
            float f0 = featf(k, a4.x, c4.x, ni, nj);
            float f1 = featf(k, a4.y, c4.y, ni, nj);
            float f2 = featf(k, a4.z, c4.z, ni, nj);
            float f3 = featf(k, a4.w, c4.w, ni, nj);
            u32 h01, l01, h23, l23;
            split2(f0, f1, h01, l01);
            split2(f2, f3, h23, l23);
            int widx = p*68 + d4/2;
            *(uint2*)(fhw + widx) = make_uint2(h01, h23);
            *(uint2*)(flw + widx) = make_uint2(l01, l23);
        }
        CPA_WAIT0();
        __syncthreads();

        // ---- S2: issue G_hi -> WS1; h = relu(feats @ W1 + b1) (B = WS0) ----
        #pragma unroll
        for (int i = 0; i < 8; i++) {
            int idx = tid + i*256;              // [256 n][72 k] bf16 panel
            int n = idx >> 3, c8 = idx & 7;
            cpa16(sb + OFF_WS1 + n*144 + c8*16, &g_gt[k][0][n*64 + c8*8]);
        }
        CPA_COMMIT();
        {
            const int mt = wid >> 1, nh = wid & 1;
            const int arow = mt*16 + g;
            const u32* w1h = ws0w;                // [64][68] u32 rows
            const u32* w1l = ws0w + 4352;         // +17408B
            float hacc[4][4];
            #pragma unroll
            for (int nt = 0; nt < 4; nt++)
                #pragma unroll
                for (int e = 0; e < 4; e++) hacc[nt][e] = 0.f;
            #pragma unroll 1
            for (int ks = 0; ks < 8; ks++) {
                int base0 = arow*68 + ks*8 + t;
                int base1 = base0 + 8*68;
                u32 ah0 = fhw[base0], ah1 = fhw[base1], ah2 = fhw[base0+4], ah3 = fhw[base1+4];
                u32 al0 = flw[base0], al1 = flw[base1], al2 = flw[base0+4], al3 = flw[base1+4];
                #pragma unroll
                for (int nt = 0; nt < 4; nt++) {
                    int bn = nh*32 + nt*8 + g;
                    int bidx = bn*68 + ks*8 + t;
                    u32 bh0 = w1h[bidx], bh1 = w1h[bidx+4];
                    u32 bl0 = w1l[bidx], bl1 = w1l[bidx+4];
                    mma16816(hacc[nt], ah0, ah1, ah2, ah3, bh0, bh1);
                    mma16816(hacc[nt], al0, al1, al2, al3, bh0, bh1);
                    mma16816(hacc[nt], ah0, ah1, ah2, ah3, bl0, bl1);
                }
            }
            #pragma unroll
            for (int nt = 0; nt < 4; nt++) {
                int col = nh*32 + nt*8 + t2;
                float b0 = ob1[w*64 + col], b1v = ob1[w*64 + col + 1];
                float v0 = hacc[nt][0] + b0, v1 = hacc[nt][1] + b1v;
                float v2 = hacc[nt][2] + b0, v3 = hacc[nt][3] + b1v;
                v0 = v0 > 0.f ? v0 : 0.f; v1 = v1 > 0.f ? v1 : 0.f;
                v2 = v2 > 0.f ? v2 : 0.f; v3 = v3 > 0.f ? v3 : 0.f;
                u32 hp, lp;
                int cw = col/2;
                split2(v0, v1, hp, lp);
                hhw[arow*36 + cw] = hp; hlw[arow*36 + cw] = lp;
                split2(v2, v3, hp, lp);
                hhw[(arow+8)*36 + cw] = hp; hlw[(arow+8)*36 + cw] = lp;
            }
        }
        CPA_WAIT0();
        __syncthreads();

        // ---- S3: issue G_lo -> WS0; acc += (Ah+Al) @ G_hi (B = WS1) ----
        #pragma unroll
        for (int i = 0; i < 8; i++) {
            int idx = tid + i*256;
            int n = idx >> 3, c8 = idx & 7;
            cpa16(sb + OFF_WS0 + n*144 + c8*16, &g_gt[k][1][n*64 + c8*8]);
        }
        CPA_COMMIT();
        #pragma unroll 1
        for (int ks = 0; ks < 4; ks++) {
            u32 ah[2][4], al[2][4];
            #pragma unroll
            for (int mt2 = 0; mt2 < 2; mt2++) {
                int row = mh*32 + mt2*16 + g;
                int base0 = row*36 + ks*8 + t;
                int base1 = base0 + 8*36;
                ah[mt2][0] = hhw[base0]; ah[mt2][1] = hhw[base1];
                ah[mt2][2] = hhw[base0+4]; ah[mt2][3] = hhw[base1+4];
                al[mt2][0] = hlw[base0]; al[mt2][1] = hlw[base1];
                al[mt2][2] = hlw[base0+4]; al[mt2][3] = hlw[base1+4];
            }
            #pragma unroll
            for (int nt = 0; nt < 8; nt++) {
                int bn = nq*64 + nt*8 + g;
                int bidx = bn*36 + ks*8 + t;
                u32 b0 = ws1w[bidx], b1 = ws1w[bidx+4];
                #pragma unroll
                for (int mt2 = 0; mt2 < 2; mt2++) {
                    mma16816(acc[mt2][nt], ah[mt2][0], ah[mt2][1], ah[mt2][2], ah[mt2][3], b0, b1);
                    mma16816(acc[mt2][nt], al[mt2][0], al[mt2][1], al[mt2][2], al[mt2][3], b0, b1);
                }
            }
        }
        CPA_WAIT0();
        __syncthreads();

        // ---- S4: acc += Ah @ G_lo (B = WS0) ----
        #pragma unroll 1
        for (int ks = 0; ks < 4; ks++) {
            u32 ah[2][4];
            #pragma unroll
            for (int mt2 = 0; mt2 < 2; mt2++) {
                int row = mh*32 + mt2*16 + g;
                int base0 = row*36 + ks*8 + t;
                int base1 = base0 + 8*36;
                ah[mt2][0] = hhw[base0]; ah[mt2][1] = hhw[base1];
                ah[mt2][2] = hhw[base0+4]; ah[mt2][3] = hhw[base1+4];
            }
            #pragma unroll
            for (int nt = 0; nt < 8; nt++) {
                int bn = nq*64 + nt*8 + g;
                int bidx = bn*36 + ks*8 + t;
                u32 b0 = ws0w[bidx], b1 = ws0w[bidx+4];
                #pragma unroll
                for (int mt2 = 0; mt2 < 2; mt2++)
                    mma16816(acc[mt2][nt], ah[mt2][0], ah[mt2][1], ah[mt2][2], ah[mt2][3], b0, b1);
            }
        }
        __syncthreads();
    }

    // ---- F1: hid epilogue -> bf16 hi/lo panels [64][264]; stage fW2 kc0 ----
    u32* hidh = (u32*)(smc + OFF_HIDH);   // stride 132 u32
    u32* hidl = (u32*)(smc + OFF_HIDL);
    #pragma unroll
    for (int i = 0; i < 8; i++) {         // fW2 kc0: hi->WS0, lo->WS1, [128][136] panels
        int idx = tid + i*256;
        int n = idx >> 4, c8 = idx & 15;
        cpa16(sb + OFF_WS0 + n*272 + c8*16, &g_fw2t[0][n*256 + c8*8]);
        cpa16(sb + OFF_WS1 + n*272 + c8*16, &g_fw2t[1][n*256 + c8*8]);
    }
    CPA_COMMIT();
    #pragma unroll
    for (int mt2 = 0; mt2 < 2; mt2++) {
        #pragma unroll
        for (int nt = 0; nt < 8; nt++) {
            int row = mh*32 + mt2*16 + g;
            float v0 = acc[mt2][nt][0] > 0.f ? acc[mt2][nt][0] : 0.f;
            float v1 = acc[mt2][nt][1] > 0.f ? acc[mt2][nt][1] : 0.f;
            float v2 = acc[mt2][nt][2] > 0.f ? acc[mt2][nt][2] : 0.f;
            float v3 = acc[mt2][nt][3] > 0.f ? acc[mt2][nt][3] : 0.f;
            int cw = nq*32 + nt*4 + t;
            u32 hp, lp;
            split2(v0, v1, hp, lp);
            hidh[row*132 + cw] = hp; hidl[row*132 + cw] = lp;
            split2(v2, v3, hp, lp);
            hidh[(row+8)*132 + cw] = hp; hidl[(row+8)*132 + cw] = lp;
        }
    }
    CPA_WAIT0();
    __syncthreads();

    // ---- F2..F4: out = relu(hid) @ fW2 + fb2 via mma: warps 4m x 2n(64) ----
    {
        const int mt = wid >> 1, nh = wid & 1;
        const int arow = mt*16 + g;
        float acc2[8][4];
        #pragma unroll
        for (int nt = 0; nt < 8; nt++)
            #pragma unroll
            for (int e = 0; e < 4; e++) acc2[nt][e] = 0.f;

        #pragma unroll 1
        for (int kc = 0; kc < 2; kc++) {
            if (kc == 1) {
                #pragma unroll
                for (int i = 0; i < 8; i++) {
                    int idx = tid + i*256;
                    int n = idx >> 4, c8 = idx & 15;
                    cpa16(sb + OFF_WS0 + n*272 + c8*16, &g_fw2t[0][n*256 + 128 + c8*8]);
                    cpa16(sb + OFF_WS1 + n*272 + c8*16, &g_fw2t[1][n*256 + 128 + c8*8]);
                }
                CPA_COMMIT();
                CPA_WAIT0();
                __syncthreads();
            }
            #pragma unroll 1
            for (int ks = 0; ks < 8; ks++) {
                int base0 = arow*132 + kc*64 + ks*8 + t;
                int base1 = base0 + 8*132;
                u32 ah0 = hidh[base0], ah1 = hidh[base1], ah2 = hidh[base0+4], ah3 = hidh[base1+4];
                u32 al0 = hidl[base0], al1 = hidl[base1], al2 = hidl[base0+4], al3 = hidl[base1+4];
                #pragma unroll
                for (int nt = 0; nt < 8; nt++) {
                    int bn = nh*64 + nt*8 + g;
                    int bidx = bn*68 + ks*8 + t;
                    u32 bh0 = ws0w[bidx], bh1 = ws0w[bidx+4];
                    u32 bl0 = ws1w[bidx], bl1 = ws1w[bidx+4];
                    mma16816(acc2[nt], ah0, ah1, ah2, ah3, bh0, bh1);
                    mma16816(acc2[nt], al0, al1, al2, al3, bh0, bh1);
                    mma16816(acc2[nt], ah0, ah1, ah2, ah3, bl0, bl1);
                }
            }
            if (kc == 0) __syncthreads();
        }

        // epilogue: + fb2, store to gmem
        #pragma unroll
        for (int nt = 0; nt < 8; nt++) {
            int col = nh*64 + nt*8 + t2;
            float b0 = fb2[col], b1v = fb2[col + 1];
            int r0 = mt*16 + g, r1 = r0 + 8;
            if (p0 + r0 < Pp) {
                float2 v = make_float2(acc2[nt][0] + b0, acc2[nt][1] + b1v);
                *(float2*)(out + ((size_t)(b*Pp + p0 + r0))*128 + col) = v;
            }
            if (p0 + r1 < Pp) {
                float2 v = make_float2(acc2[nt][2] + b0, acc2[nt][3] + b1v);
                *(float2*)(out + ((size_t)(b*Pp + p0 + r1))*128 + col) = v;
            }
        }
    }
}

extern "C" void kernel_launch(void* const* d_in, const int* in_sizes, int n_in,
                              void* d_out, int out_size) {
    const float* x        = (const float*)d_in[0];
    const int*   presence = (const int*)d_in[1];
    const int*   idx_i    = (const int*)d_in[2];
    const int*   idx_j    = (const int*)d_in[3];
    const float* oW1      = (const float*)d_in[4];
    const float* ob1      = (const float*)d_in[5];
    const float* oW2      = (const float*)d_in[6];
    const float* ob2      = (const float*)d_in[7];
    const float* pW1      = (const float*)d_in[8];
    const float* pb1      = (const float*)d_in[9];
    const float* pW2      = (const float*)d_in[10];
    const float* pb2      = (const float*)d_in[11];
    const float* fW1      = (const float*)d_in[12];
    const float* fb1      = (const float*)d_in[13];
    const float* fW2      = (const float*)d_in[14];
    const float* fb2      = (const float*)d_in[15];

    conv_kernel<<<1024, 256>>>(fW1, oW1, oW2, ob2, fW2);

    cudaFuncSetAttribute(dre_kernel, cudaFuncAttributeMaxDynamicSharedMemorySize, SMEM_BYTES);
    dre_kernel<<<2048, 256, SMEM_BYTES>>>(x, presence, idx_i, idx_j,
                                          oW1, ob1, oW2, ob2,
                                          pW1, pb1, pW2, pb2,
                                          fW1, fb1, fW2, fb2,
                                          (float*)d_out);
}

// round 12
// speedup vs baseline: 3.4400x; 1.1386x over previous
#include <cuda_runtime.h>
#include <cuda_bf16.h>
#include <cstdint>

// DynamicRelationshipExtractor — GB300 sm_103a, round 12
// = round 11 algorithm with 512 threads/CTA (16 warps = 4/SMSP) to hide
//   LDS/mma latency; all warp tiles halved, work per CTA identical.

#define EPSF 1e-6f
#define NT 512

static const int NC = 64;
static const int Dd = 128;
static const int Pp = 2016;
static const int TP = 64;

typedef unsigned long long u64;
typedef unsigned int u32;

__device__ __forceinline__ void mma16816(float* c, u32 a0, u32 a1, u32 a2, u32 a3,
                                         u32 b0, u32 b1) {
    asm volatile(
        "mma.sync.aligned.m16n8k16.row.col.f32.bf16.bf16.f32 "
        "{%0,%1,%2,%3},{%4,%5,%6,%7},{%8,%9},{%0,%1,%2,%3};"
        : "+f"(c[0]), "+f"(c[1]), "+f"(c[2]), "+f"(c[3])
        : "r"(a0), "r"(a1), "r"(a2), "r"(a3), "r"(b0), "r"(b1));
}

__device__ __forceinline__ void split2(float a, float b, u32 &hp, u32 &lp) {
    __nv_bfloat16 ha = __float2bfloat16(a), hb_ = __float2bfloat16(b);
    __nv_bfloat16 la = __float2bfloat16(a - __bfloat162float(ha));
    __nv_bfloat16 lb = __float2bfloat16(b - __bfloat162float(hb_));
    hp = ((u32)__bfloat16_as_ushort(hb_) << 16) | (u32)__bfloat16_as_ushort(ha);
    lp = ((u32)__bfloat16_as_ushort(lb)  << 16) | (u32)__bfloat16_as_ushort(la);
}

__device__ __forceinline__ u32 smem_u32(const void* p) {
    u32 a; asm("{ .reg .u64 t; cvta.to.shared.u64 t, %1; cvt.u32.u64 %0, t; }" : "=r"(a) : "l"(p));
    return a;
}
__device__ __forceinline__ void cpa16(u32 dst, const void* src) {
    asm volatile("cp.async.cg.shared.global [%0], [%1], 16;"
                 :: "r"(dst), "l"(__cvta_generic_to_global(src)));
}
#define CPA_COMMIT() asm volatile("cp.async.commit_group;" ::: "memory")
#define CPA_WAIT0()  asm volatile("cp.async.wait_group 0;" ::: "memory")

// precomputed weight images (bf16 hi/lo, B-operand [n][k] layouts)
__device__ __align__(16) __nv_bfloat16 g_ow1t[6][2][8192];   // W1^T: [64 n(j)][128 k(d)]
__device__ __align__(16) __nv_bfloat16 g_gt[8][2][16384];    // G_k^T: [256 n(q)][64 k(j)]
__device__ __align__(16) __nv_bfloat16 g_fw2t[2][32768];     // fW2^T: [128 n(d)][256 k(q)]
__device__ float g_csum[256];                                 // sum_k b2@fW1_k

__global__ void conv_kernel(const float* __restrict__ fW1,
                            const float* __restrict__ oW1,
                            const float* __restrict__ oW2,
                            const float* __restrict__ ob2,
                            const float* __restrict__ fW2) {
    const int mlp_idx[8] = {0, 1, 2, 3, 4, 4, 5, 5};
    int idx = blockIdx.x * blockDim.x + threadIdx.x;   // 0..262143

    // G_k[j][q] = sum_d W2[w(k)][j][d] * fW1[k*128+d][q], stored ^T [q][j]
    if (idx < 131072) {
        int kidx = idx >> 14;
        int e = idx & 16383;
        int q = e & 255, j = e >> 8;
        int w = mlp_idx[kidx];
        const float* w2row = oW2 + (size_t)w*8192 + j*128;
        const float* f1col = fW1 + (size_t)kidx*128*256 + q;
        float s = 0.f;
        #pragma unroll 8
        for (int d = 0; d < 128; d++) s = fmaf(w2row[d], f1col[(size_t)d*256], s);
        __nv_bfloat16 hi = __float2bfloat16(s);
        __nv_bfloat16 lo = __float2bfloat16(s - __bfloat162float(hi));
        g_gt[kidx][0][q*64 + j] = hi;
        g_gt[kidx][1][q*64 + j] = lo;
    }
    if (idx < 49152) {
        int w = idx >> 13;
        int e = idx & 8191;
        int n = e >> 7, kk = e & 127;       // n=j, k=d
        float v = oW1[(size_t)w*8192 + kk*64 + n];
        __nv_bfloat16 hi = __float2bfloat16(v);
        __nv_bfloat16 lo = __float2bfloat16(v - __bfloat162float(hi));
        g_ow1t[w][0][n*128 + kk] = hi;
        g_ow1t[w][1][n*128 + kk] = lo;
    }
    if (idx < 32768) {
        int n = idx >> 8, kk = idx & 255;   // n=d(128), k=q(256)
        float v = fW2[(size_t)kk*128 + n];
        __nv_bfloat16 hi = __float2bfloat16(v);
        __nv_bfloat16 lo = __float2bfloat16(v - __bfloat162float(hi));
        g_fw2t[0][n*256 + kk] = hi;
        g_fw2t[1][n*256 + kk] = lo;
    }
    if (idx < 256) {
        int q = idx;
        float s = 0.f;
        for (int kk = 0; kk < 8; kk++) {
            int w = mlp_idx[kk];
            const float* b2r = ob2 + w*128;
            const float* f1c = fW1 + (size_t)kk*128*256 + q;
            #pragma unroll 8
            for (int d = 0; d < 128; d++) s = fmaf(b2r[d], f1c[(size_t)d*256], s);
        }
        g_csum[q] = s;
    }
}

// ---- shared layout (BYTE offsets) ----
#define OFF_XS     0          // 32768 (fp32 x[b])
#define OFF_FH     32768      // [64][136] bf16 = 17408
#define OFF_FL     50176      // 17408 -> 67584
#define OFF_HH     67584      // [64][72] bf16 = 9216
#define OFF_HL     76800      // 9216 -> 86016
#define OFF_WS0    86016      // 36864 ping -> 122880
#define OFF_WS1    122880     // 36864 pong -> 159744
#define OFF_PCON   159744     // 1024 fl -> 163840
#define OFF_PTOK4  163840     // 512 fl -> 165888
#define OFF_PH4    165888     // 256 fl -> 166912
#define OFF_INORM  166912     // 64 fl -> 167168
#define OFF_INTS   167168     // 3*64 int -> 167936
#define SMEM_BYTES 167936
// hid bf16 panels alias [0, 67584): hi [64][264] at 0, lo at 33792
#define OFF_HIDH   0
#define OFF_HIDL   33792

__device__ __forceinline__ float featf(int k, float a, float c, float ni, float nj) {
    switch (k) {
        case 0: return a * c;
        case 1: return a + c;
        case 2: return (a * ni) * (c * nj);
        case 3: return fabsf(a - c);
        case 4: return a - c;
        case 5: return c - a;
        case 6: return __fdiv_rn(a, c + EPSF);
        default: return __fdiv_rn(c, a + EPSF);
    }
}

__global__ void __launch_bounds__(NT, 1)
dre_kernel(const float* __restrict__ x, const int* __restrict__ presence,
           const int* __restrict__ idx_i, const int* __restrict__ idx_j,
           const float* __restrict__ oW1, const float* __restrict__ ob1,
           const float* __restrict__ oW2, const float* __restrict__ ob2,
           const float* __restrict__ pW1, const float* __restrict__ pb1,
           const float* __restrict__ pW2, const float* __restrict__ pb2,
           const float* __restrict__ fW1, const float* __restrict__ fb1,
           const float* __restrict__ fW2, const float* __restrict__ fb2,
           float* __restrict__ out)
{
    extern __shared__ float sm[];
    char*  smc   = (char*)sm;
    float* xs    = (float*)(smc + OFF_XS);
    u32*   fhw   = (u32*)(smc + OFF_FH);
    u32*   flw   = (u32*)(smc + OFF_FL);
    u32*   hhw   = (u32*)(smc + OFF_HH);
    u32*   hlw   = (u32*)(smc + OFF_HL);
    u32*   ws0w  = (u32*)(smc + OFF_WS0);
    u32*   ws1w  = (u32*)(smc + OFF_WS1);
    float* pcon  = (float*)(smc + OFF_PCON);
    float* ptok4 = (float*)(smc + OFF_PTOK4);
    float* ph4   = (float*)(smc + OFF_PH4);
    float* inorm = (float*)(smc + OFF_INORM);
    int*   pi    = (int*)(smc + OFF_INTS);
    int*   pj    = pi + 64;
    int*   pcx   = pj + 64;

    const int tid = threadIdx.x;
    const int b   = blockIdx.x >> 5;
    const int p0  = (blockIdx.x & 31) * TP;
    const int wid = tid >> 5, lane = tid & 31;
    const int g   = lane >> 2;          // frag row group 0..7
    const int t   = lane & 3;           // frag k-word 0..3
    const int t2  = t * 2;
    const u32 sb  = smem_u32(sm);

    // ---- load x[b] ----
    {
        const float4* src = (const float4*)(x + (size_t)b * NC * Dd);
        float4* dst = (float4*)xs;
        #pragma unroll
        for (int i = 0; i < 4; i++) dst[tid + i*NT] = src[tid + i*NT];
    }
    if (tid < TP) {
        int pp = p0 + tid; if (pp >= Pp) pp = Pp - 1;
        int ii = idx_i[pp], jj = idx_j[pp];
        pi[tid] = ii; pj[tid] = jj;
        int pa = presence[b*NC + ii], pb_ = presence[b*NC + jj];
        pcx[tid] = pa ? (pb_ ? 0 : 1) : (pb_ ? 2 : 3);
    }
    if (tid < 256) {
        int c = tid >> 6, tt = tid & 63;
        float v = pW1[c*64 + tt] + pb1[tt];
        ph4[tid] = v > 0.f ? v : 0.f;
    }
    __syncthreads();

    if (tid < NC) {
        float s = 0.f;
        const float* row = xs + tid * Dd;
        #pragma unroll 8
        for (int d = 0; d < Dd; d++) { float v = row[d]; s = fmaf(v, v, s); }
        inorm[tid] = __fdiv_rn(1.f, __fsqrt_rn(s) + EPSF);
    }
    if (tid < 512) {
        int o = tid;
        int c = o >> 7, d = o & 127;
        float s = pb2[d];
        const float* ph = ph4 + c*64;
        #pragma unroll 8
        for (int tt = 0; tt < 64; tt++) s = fmaf(ph[tt], pW2[tt*128 + d], s);
        ptok4[o] = s;
    }
    __syncthreads();
    for (int o = tid; o < 1024; o += NT) {
        int c = o >> 8, q = o & 255;
        float s = 0.f;
        const float* pt = ptok4 + c*128;
        #pragma unroll 8
        for (int d = 0; d < 128; d++) s = fmaf(pt[d], fW1[(size_t)(1024 + d)*256 + q], s);
        pcon[o] = s;
    }
    __syncthreads();

    // ---- hid accumulator fragments: 16 warps as 2m x 8n ----
    const int mh = wid & 1;        // rows mh*32 .. +31
    const int nq = wid >> 1;       // cols nq*32 .. +31 (4 ntiles)
    float acc[2][4][4];
    #pragma unroll
    for (int mt2 = 0; mt2 < 2; mt2++) {
        int row = mh*32 + mt2*16 + g;
        int c0 = pcx[row], c1 = pcx[row + 8];
        #pragma unroll
        for (int nt = 0; nt < 4; nt++) {
            int q = nq*32 + nt*8 + t2;
            float cs0 = g_csum[q], cs1 = g_csum[q+1];
            acc[mt2][nt][0] = fb1[q]   + pcon[c0*256 + q]     + cs0;
            acc[mt2][nt][1] = fb1[q+1] + pcon[c0*256 + q + 1] + cs1;
            acc[mt2][nt][2] = fb1[q]   + pcon[c1*256 + q]     + cs0;
            acc[mt2][nt][3] = fb1[q+1] + pcon[c1*256 + q + 1] + cs1;
        }
    }

    const int mlp_idx[8] = {0, 1, 2, 3, 4, 4, 5, 5};

    #pragma unroll 1
    for (int k = 0; k < 8; k++) {
        const int w = mlp_idx[k];

        // ---- S1: cp.async W1 -> WS0 [copy][64][136]; feats -> fh/fl ----
        #pragma unroll
        for (int i = 0; i < 4; i++) {
            int idx = tid + i*NT;               // 0..2047
            int c = idx >> 10, e = idx & 1023;
            int n = e >> 4, c8 = e & 15;
            cpa16(sb + OFF_WS0 + c*17408 + n*272 + c8*16, &g_ow1t[w][c][n*128 + c8*8]);
        }
        CPA_COMMIT();

        #pragma unroll 1
        for (int it = 0; it < 4; it++) {
            int o = tid + it*NT;
            int p = o >> 5, d4 = (o & 31) * 4;
            int ci = pi[p], cj = pj[p];
            float4 a4 = *(const float4*)(xs + ci*Dd + d4);
            float4 c4 = *(const float4*)(xs + cj*Dd + d4);
            float ni = inorm[ci], nj = inorm[cj];
            float f0 = featf(k, a4.x, c4.x, ni, nj);
            float f1 = featf(k, a4.y, c4.y, ni, nj);
            float f2 = featf(k, a4.z, c4.z, ni, nj);
            float f3 = featf(k, a4.w, c4.w, ni, nj);
            u32 h01, l01, h23, l23;
            split2(f0, f1, h01, l01);
            split2(f2, f3, h23, l23);
            int widx = p*68 + d4/2;
            *(uint2*)(fhw + widx) = make_uint2(h01, h23);
            *(uint2*)(flw + widx) = make_uint2(l01, l23);
        }
        CPA_WAIT0();
        __syncthreads();

        // ---- S2: issue G_hi -> WS1; h = relu(feats @ W1 + b1): 4m x 4n ----
        #pragma unroll
        for (int i = 0; i < 4; i++) {
            int idx = tid + i*NT;               // [256 n][72 k] bf16 panel
            int n = idx >> 3, c8 = idx & 7;
            cpa16(sb + OFF_WS1 + n*144 + c8*16, &g_gt[k][0][n*64 + c8*8]);
        }
        CPA_COMMIT();
        {
            const int mt = wid >> 2, nh = wid & 3;
            const int arow = mt*16 + g;
            const u32* w1h = ws0w;                // [64][68] u32 rows
            const u32* w1l = ws0w + 4352;         // +17408B
            float hacc[2][4];
            #pragma unroll
            for (int nt = 0; nt < 2; nt++)
                #pragma unroll
                for (int e = 0; e < 4; e++) hacc[nt][e] = 0.f;
            #pragma unroll 1
            for (int ks = 0; ks < 8; ks++) {
                int base0 = arow*68 + ks*8 + t;
                int base1 = base0 + 8*68;
                u32 ah0 = fhw[base0], ah1 = fhw[base1], ah2 = fhw[base0+4], ah3 = fhw[base1+4];
                u32 al0 = flw[base0], al1 = flw[base1], al2 = flw[base0+4], al3 = flw[base1+4];
                #pragma unroll
                for (int nt = 0; nt < 2; nt++) {
                    int bn = nh*16 + nt*8 + g;
                    int bidx = bn*68 + ks*8 + t;
                    u32 bh0 = w1h[bidx], bh1 = w1h[bidx+4];
                    u32 bl0 = w1l[bidx], bl1 = w1l[bidx+4];
                    mma16816(hacc[nt], ah0, ah1, ah2, ah3, bh0, bh1);
                    mma16816(hacc[nt], al0, al1, al2, al3, bh0, bh1);
                    mma16816(hacc[nt], ah0, ah1, ah2, ah3, bl0, bl1);
                }
            }
            #pragma unroll
            for (int nt = 0; nt < 2; nt++) {
                int col = nh*16 + nt*8 + t2;
                float b0 = ob1[w*64 + col], b1v = ob1[w*64 + col + 1];
                float v0 = hacc[nt][0] + b0, v1 = hacc[nt][1] + b1v;
                float v2 = hacc[nt][2] + b0, v3 = hacc[nt][3] + b1v;
                v0 = v0 > 0.f ? v0 : 0.f; v1 = v1 > 0.f ? v1 : 0.f;
                v2 = v2 > 0.f ? v2 : 0.f; v3 = v3 > 0.f ? v3 : 0.f;
                u32 hp, lp;
                int cw = col/2;
                split2(v0, v1, hp, lp);
                hhw[arow*36 + cw] = hp; hlw[arow*36 + cw] = lp;
                split2(v2, v3, hp, lp);
                hhw[(arow+8)*36 + cw] = hp; hlw[(arow+8)*36 + cw] = lp;
            }
        }
        CPA_WAIT0();
        __syncthreads();

        // ---- S3: issue G_lo -> WS0; acc += (Ah+Al) @ G_hi (B = WS1) ----
        #pragma unroll
        for (int i = 0; i < 4; i++) {
            int idx = tid + i*NT;
            int n = idx >> 3, c8 = idx & 7;
            cpa16(sb + OFF_WS0 + n*144 + c8*16, &g_gt[k][1][n*64 + c8*8]);
        }
        CPA_COMMIT();
        #pragma unroll 1
        for (int ks = 0; ks < 4; ks++) {
            u32 ah[2][4], al[2][4];
            #pragma unroll
            for (int mt2 = 0; mt2 < 2; mt2++) {
                int row = mh*32 + mt2*16 + g;
                int base0 = row*36 + ks*8 + t;
                int base1 = base0 + 8*36;
                ah[mt2][0] = hhw[base0]; ah[mt2][1] = hhw[base1];
                ah[mt2][2] = hhw[base0+4]; ah[mt2][3] = hhw[base1+4];
                al[mt2][0] = hlw[base0]; al[mt2][1] = hlw[base1];
                al[mt2][2] = hlw[base0+4]; al[mt2][3] = hlw[base1+4];
            }
            #pragma unroll
            for (int nt = 0; nt < 4; nt++) {
                int bn = nq*32 + nt*8 + g;
                int bidx = bn*36 + ks*8 + t;
                u32 b0 = ws1w[bidx], b1 = ws1w[bidx+4];
                #pragma unroll
                for (int mt2 = 0; mt2 < 2; mt2++) {
                    mma16816(acc[mt2][nt], ah[mt2][0], ah[mt2][1], ah[mt2][2], ah[mt2][3], b0, b1);
                    mma16816(acc[mt2][nt], al[mt2][0], al[mt2][1], al[mt2][2], al[mt2][3], b0, b1);
                }
            }
        }
        CPA_WAIT0();
        __syncthreads();

        // ---- S4: acc += Ah @ G_lo (B = WS0) ----
        #pragma unroll 1
        for (int ks = 0; ks < 4; ks++) {
            u32 ah[2][4];
            #pragma unroll
            for (int mt2 = 0; mt2 < 2; mt2++) {
                int row = mh*32 + mt2*16 + g;
                int base0 = row*36 + ks*8 + t;
                int base1 = base0 + 8*36;
                ah[mt2][0] = hhw[base0]; ah[mt2][1] = hhw[base1];
                ah[mt2][2] = hhw[base0+4]; ah[mt2][3] = hhw[base1+4];
            }
            #pragma unroll
            for (int nt = 0; nt < 4; nt++) {
                int bn = nq*32 + nt*8 + g;
                int bidx = bn*36 + ks*8 + t;
                u32 b0 = ws0w[bidx], b1 = ws0w[bidx+4];
                #pragma unroll
                for (int mt2 = 0; mt2 < 2; mt2++)
                    mma16816(acc[mt2][nt], ah[mt2][0], ah[mt2][1], ah[mt2][2], ah[mt2][3], b0, b1);
            }
        }
        __syncthreads();
    }

    // ---- F1: hid epilogue -> bf16 hi/lo panels [64][264]; stage fW2 kc0 ----
    u32* hidh = (u32*)(smc + OFF_HIDH);   // stride 132 u32
    u32* hidl = (u32*)(smc + OFF_HIDL);
    #pragma unroll
    for (int i = 0; i < 4; i++) {         // fW2 kc0: hi->WS0, lo->WS1, [128][136] panels
        int idx = tid + i*NT;
        int n = idx >> 4, c8 = idx & 15;
        cpa16(sb + OFF_WS0 + n*272 + c8*16, &g_fw2t[0][n*256 + c8*8]);
        cpa16(sb + OFF_WS1 + n*272 + c8*16, &g_fw2t[1][n*256 + c8*8]);
    }
    CPA_COMMIT();
    #pragma unroll
    for (int mt2 = 0; mt2 < 2; mt2++) {
        #pragma unroll
        for (int nt = 0; nt < 4; nt++) {
            int row = mh*32 + mt2*16 + g;
            float v0 = acc[mt2][nt][0] > 0.f ? acc[mt2][nt][0] : 0.f;
            float v1 = acc[mt2][nt][1] > 0.f ? acc[mt2][nt][1] : 0.f;
            float v2 = acc[mt2][nt][2] > 0.f ? acc[mt2][nt][2] : 0.f;
            float v3 = acc[mt2][nt][3] > 0.f ? acc[mt2][nt][3] : 0.f;
            int cw = nq*16 + nt*4 + t;
            u32 hp, lp;
            split2(v0, v1, hp, lp);
            hidh[row*132 + cw] = hp; hidl[row*132 + cw] = lp;
            split2(v2, v3, hp, lp);
            hidh[(row+8)*132 + cw] = hp; hidl[(row+8)*132 + cw] = lp;
        }
    }
    CPA_WAIT0();
    __syncthreads();

    // ---- F2..F4: out = relu(hid) @ fW2 + fb2 via mma: 4m x 4n(32) ----
    {
        const int mt = wid >> 2, nh = wid & 3;
        const int arow = mt*16 + g;
        float acc2[4][4];
        #pragma unroll
        for (int nt = 0; nt < 4; nt++)
            #pragma unroll
            for (int e = 0; e < 4; e++) acc2[nt][e] = 0.f;

        #pragma unroll 1
        for (int kc = 0; kc < 2; kc++) {
            if (kc == 1) {
                #pragma unroll
                for (int i = 0; i < 4; i++) {
                    int idx = tid + i*NT;
                    int n = idx >> 4, c8 = idx & 15;
                    cpa16(sb + OFF_WS0 + n*272 + c8*16, &g_fw2t[0][n*256 + 128 + c8*8]);
                    cpa16(sb + OFF_WS1 + n*272 + c8*16, &g_fw2t[1][n*256 + 128 + c8*8]);
                }
                CPA_COMMIT();
                CPA_WAIT0();
                __syncthreads();
            }
            #pragma unroll 1
            for (int ks = 0; ks < 8; ks++) {
                int base0 = arow*132 + kc*64 + ks*8 + t;
                int base1 = base0 + 8*132;
                u32 ah0 = hidh[base0], ah1 = hidh[base1], ah2 = hidh[base0+4], ah3 = hidh[base1+4];
                u32 al0 = hidl[base0], al1 = hidl[base1], al2 = hidl[base0+4], al3 = hidl[base1+4];
                #pragma unroll
                for (int nt = 0; nt < 4; nt++) {
                    int bn = nh*32 + nt*8 + g;
                    int bidx = bn*68 + ks*8 + t;
                    u32 bh0 = ws0w[bidx], bh1 = ws0w[bidx+4];
                    u32 bl0 = ws1w[bidx], bl1 = ws1w[bidx+4];
                    mma16816(acc2[nt], ah0, ah1, ah2, ah3, bh0, bh1);
                    mma16816(acc2[nt], al0, al1, al2, al3, bh0, bh1);
                    mma16816(acc2[nt], ah0, ah1, ah2, ah3, bl0, bl1);
                }
            }
            if (kc == 0) __syncthreads();
        }

        // epilogue: + fb2, store to gmem
        #pragma unroll
        for (int nt = 0; nt < 4; nt++) {
            int col = nh*32 + nt*8 + t2;
            float b0 = fb2[col], b1v = fb2[col + 1];
            int r0 = mt*16 + g, r1 = r0 + 8;
            if (p0 + r0 < Pp) {
                float2 v = make_float2(acc2[nt][0] + b0, acc2[nt][1] + b1v);
                *(float2*)(out + ((size_t)(b*Pp + p0 + r0))*128 + col) = v;
            }
            if (p0 + r1 < Pp) {
                float2 v = make_float2(acc2[nt][2] + b0, acc2[nt][3] + b1v);
                *(float2*)(out + ((size_t)(b*Pp + p0 + r1))*128 + col) = v;
            }
        }
    }
}

extern "C" void kernel_launch(void* const* d_in, const int* in_sizes, int n_in,
                              void* d_out, int out_size) {
    const float* x        = (const float*)d_in[0];
    const int*   presence = (const int*)d_in[1];
    const int*   idx_i    = (const int*)d_in[2];
    const int*   idx_j    = (const int*)d_in[3];
    const float* oW1      = (const float*)d_in[4];
    const float* ob1      = (const float*)d_in[5];
    const float* oW2      = (const float*)d_in[6];
    const float* ob2      = (const float*)d_in[7];
    const float* pW1      = (const float*)d_in[8];
    const float* pb1      = (const float*)d_in[9];
    const float* pW2      = (const float*)d_in[10];
    const float* pb2      = (const float*)d_in[11];
    const float* fW1      = (const float*)d_in[12];
    const float* fb1      = (const float*)d_in[13];
    const float* fW2      = (const float*)d_in[14];
    const float* fb2      = (const float*)d_in[15];

    conv_kernel<<<1024, 256>>>(fW1, oW1, oW2, ob2, fW2);

    cudaFuncSetAttribute(dre_kernel, cudaFuncAttributeMaxDynamicSharedMemorySize, SMEM_BYTES);
    dre_kernel<<<2048, NT, SMEM_BYTES>>>(x, presence, idx_i, idx_j,
                                         oW1, ob1, oW2, ob2,
                                         pW1, pb1, pW2, pb2,
                                         fW1, fb1, fW2, fb2,
                                         (float*)d_out);
}

// round 13
// speedup vs baseline: 3.4675x; 1.0080x over previous
#include <cuda_runtime.h>
#include <cuda_bf16.h>
#include <cstdint>

// DynamicRelationshipExtractor — GB300 sm_103a, round 13
// = round 12 + (a) third staging buffer WS2: G_hi+G_lo staged together at S1,
//   S3/S4 merged into one stage (A frags loaded once for all 3 terms, one
//   sync/phase removed), (b) W1(k+1) prefetched during S3, (c) fusion2 kc1-hi
//   prefetched at F1 and kc1-lo overlapped with the kc1 hi-term mma.

#define EPSF 1e-6f
#define NT 512

static const int NC = 64;
static const int Dd = 128;
static const int Pp = 2016;
static const int TP = 64;

typedef unsigned long long u64;
typedef unsigned int u32;

__device__ __forceinline__ void mma16816(float* c, u32 a0, u32 a1, u32 a2, u32 a3,
                                         u32 b0, u32 b1) {
    asm volatile(
        "mma.sync.aligned.m16n8k16.row.col.f32.bf16.bf16.f32 "
        "{%0,%1,%2,%3},{%4,%5,%6,%7},{%8,%9},{%0,%1,%2,%3};"
        : "+f"(c[0]), "+f"(c[1]), "+f"(c[2]), "+f"(c[3])
        : "r"(a0), "r"(a1), "r"(a2), "r"(a3), "r"(b0), "r"(b1));
}

__device__ __forceinline__ void split2(float a, float b, u32 &hp, u32 &lp) {
    __nv_bfloat16 ha = __float2bfloat16(a), hb_ = __float2bfloat16(b);
    __nv_bfloat16 la = __float2bfloat16(a - __bfloat162float(ha));
    __nv_bfloat16 lb = __float2bfloat16(b - __bfloat162float(hb_));
    hp = ((u32)__bfloat16_as_ushort(hb_) << 16) | (u32)__bfloat16_as_ushort(ha);
    lp = ((u32)__bfloat16_as_ushort(lb)  << 16) | (u32)__bfloat16_as_ushort(la);
}

__device__ __forceinline__ u32 smem_u32(const void* p) {
    u32 a; asm("{ .reg .u64 t; cvta.to.shared.u64 t, %1; cvt.u32.u64 %0, t; }" : "=r"(a) : "l"(p));
    return a;
}
__device__ __forceinline__ void cpa16(u32 dst, const void* src) {
    asm volatile("cp.async.cg.shared.global [%0], [%1], 16;"
                 :: "r"(dst), "l"(__cvta_generic_to_global(src)));
}
#define CPA_COMMIT() asm volatile("cp.async.commit_group;" ::: "memory")
#define CPA_WAIT0()  asm volatile("cp.async.wait_group 0;" ::: "memory")

// precomputed weight images (bf16 hi/lo, B-operand [n][k] layouts)
__device__ __align__(16) __nv_bfloat16 g_ow1t[6][2][8192];   // W1^T: [64 n(j)][128 k(d)]
__device__ __align__(16) __nv_bfloat16 g_gt[8][2][16384];    // G_k^T: [256 n(q)][64 k(j)]
__device__ __align__(16) __nv_bfloat16 g_fw2t[2][32768];     // fW2^T: [128 n(d)][256 k(q)]
__device__ float g_csum[256];                                 // sum_k b2@fW1_k

__global__ void conv_kernel(const float* __restrict__ fW1,
                            const float* __restrict__ oW1,
                            const float* __restrict__ oW2,
                            const float* __restrict__ ob2,
                            const float* __restrict__ fW2) {
    const int mlp_idx[8] = {0, 1, 2, 3, 4, 4, 5, 5};
    int idx = blockIdx.x * blockDim.x + threadIdx.x;   // 0..262143

    // G_k[j][q] = sum_d W2[w(k)][j][d] * fW1[k*128+d][q], stored ^T [q][j]
    if (idx < 131072) {
        int kidx = idx >> 14;
        int e = idx & 16383;
        int q = e & 255, j = e >> 8;
        int w = mlp_idx[kidx];
        const float* w2row = oW2 + (size_t)w*8192 + j*128;
        const float* f1col = fW1 + (size_t)kidx*128*256 + q;
        float s = 0.f;
        #pragma unroll 8
        for (int d = 0; d < 128; d++) s = fmaf(w2row[d], f1col[(size_t)d*256], s);
        __nv_bfloat16 hi = __float2bfloat16(s);
        __nv_bfloat16 lo = __float2bfloat16(s - __bfloat162float(hi));
        g_gt[kidx][0][q*64 + j] = hi;
        g_gt[kidx][1][q*64 + j] = lo;
    }
    if (idx < 49152) {
        int w = idx >> 13;
        int e = idx & 8191;
        int n = e >> 7, kk = e & 127;       // n=j, k=d
        float v = oW1[(size_t)w*8192 + kk*64 + n];
        __nv_bfloat16 hi = __float2bfloat16(v);
        __nv_bfloat16 lo = __float2bfloat16(v - __bfloat162float(hi));
        g_ow1t[w][0][n*128 + kk] = hi;
        g_ow1t[w][1][n*128 + kk] = lo;
    }
    if (idx < 32768) {
        int n = idx >> 8, kk = idx & 255;   // n=d(128), k=q(256)
        float v = fW2[(size_t)kk*128 + n];
        __nv_bfloat16 hi = __float2bfloat16(v);
        __nv_bfloat16 lo = __float2bfloat16(v - __bfloat162float(hi));
        g_fw2t[0][n*256 + kk] = hi;
        g_fw2t[1][n*256 + kk] = lo;
    }
    if (idx < 256) {
        int q = idx;
        float s = 0.f;
        for (int kk = 0; kk < 8; kk++) {
            int w = mlp_idx[kk];
            const float* b2r = ob2 + w*128;
            const float* f1c = fW1 + (size_t)kk*128*256 + q;
            #pragma unroll 8
            for (int d = 0; d < 128; d++) s = fmaf(b2r[d], f1c[(size_t)d*256], s);
        }
        g_csum[q] = s;
    }
}

// ---- shared layout (BYTE offsets) ----
#define OFF_XS     0          // 32768 (fp32 x[b])
#define OFF_FH     32768      // [64][136] bf16 = 17408
#define OFF_FL     50176      // 17408 -> 67584
#define OFF_HH     67584      // [64][72] bf16 = 9216
#define OFF_HL     76800      // 9216 -> 86016
#define OFF_WS0    86016      // 36864 -> 122880
#define OFF_WS1    122880     // 36864 -> 159744
#define OFF_WS2    159744     // 36864 -> 196608
#define OFF_PCON   196608     // 1024 fl -> 200704
#define OFF_PTOK4  200704     // 512 fl -> 202752
#define OFF_PH4    202752     // 256 fl -> 203776
#define OFF_INORM  203776     // 64 fl -> 204032
#define OFF_INTS   204032     // 3*64 int -> 204800
#define SMEM_BYTES 204800
// hid bf16 panels alias [0, 67584): hi [64][264] at 0, lo at 33792
#define OFF_HIDH   0
#define OFF_HIDL   33792

__device__ __forceinline__ float featf(int k, float a, float c, float ni, float nj) {
    switch (k) {
        case 0: return a * c;
        case 1: return a + c;
        case 2: return (a * ni) * (c * nj);
        case 3: return fabsf(a - c);
        case 4: return a - c;
        case 5: return c - a;
        case 6: return __fdiv_rn(a, c + EPSF);
        default: return __fdiv_rn(c, a + EPSF);
    }
}

__global__ void __launch_bounds__(NT, 1)
dre_kernel(const float* __restrict__ x, const int* __restrict__ presence,
           const int* __restrict__ idx_i, const int* __restrict__ idx_j,
           const float* __restrict__ oW1, const float* __restrict__ ob1,
           const float* __restrict__ oW2, const float* __restrict__ ob2,
           const float* __restrict__ pW1, const float* __restrict__ pb1,
           const float* __restrict__ pW2, const float* __restrict__ pb2,
           const float* __restrict__ fW1, const float* __restrict__ fb1,
           const float* __restrict__ fW2, const float* __restrict__ fb2,
           float* __restrict__ out)
{
    extern __shared__ float sm[];
    char*  smc   = (char*)sm;
    float* xs    = (float*)(smc + OFF_XS);
    u32*   fhw   = (u32*)(smc + OFF_FH);
    u32*   flw   = (u32*)(smc + OFF_FL);
    u32*   hhw   = (u32*)(smc + OFF_HH);
    u32*   hlw   = (u32*)(smc + OFF_HL);
    u32*   ws0w  = (u32*)(smc + OFF_WS0);
    u32*   ws1w  = (u32*)(smc + OFF_WS1);
    u32*   ws2w  = (u32*)(smc + OFF_WS2);
    float* pcon  = (float*)(smc + OFF_PCON);
    float* ptok4 = (float*)(smc + OFF_PTOK4);
    float* ph4   = (float*)(smc + OFF_PH4);
    float* inorm = (float*)(smc + OFF_INORM);
    int*   pi    = (int*)(smc + OFF_INTS);
    int*   pj    = pi + 64;
    int*   pcx   = pj + 64;

    const int tid = threadIdx.x;
    const int b   = blockIdx.x >> 5;
    const int p0  = (blockIdx.x & 31) * TP;
    const int wid = tid >> 5, lane = tid & 31;
    const int g   = lane >> 2;          // frag row group 0..7
    const int t   = lane & 3;           // frag k-word 0..3
    const int t2  = t * 2;
    const u32 sb  = smem_u32(sm);

    const int mlp_idx[8] = {0, 1, 2, 3, 4, 4, 5, 5};

    // ---- load x[b] ----
    {
        const float4* src = (const float4*)(x + (size_t)b * NC * Dd);
        float4* dst = (float4*)xs;
        #pragma unroll
        for (int i = 0; i < 4; i++) dst[tid + i*NT] = src[tid + i*NT];
    }
    if (tid < TP) {
        int pp = p0 + tid; if (pp >= Pp) pp = Pp - 1;
        int ii = idx_i[pp], jj = idx_j[pp];
        pi[tid] = ii; pj[tid] = jj;
        int pa = presence[b*NC + ii], pb_ = presence[b*NC + jj];
        pcx[tid] = pa ? (pb_ ? 0 : 1) : (pb_ ? 2 : 3);
    }
    if (tid < 256) {
        int c = tid >> 6, tt = tid & 63;
        float v = pW1[c*64 + tt] + pb1[tt];
        ph4[tid] = v > 0.f ? v : 0.f;
    }
    // prologue prefetch: W1(0) -> WS0
    #pragma unroll
    for (int i = 0; i < 4; i++) {
        int idx = tid + i*NT;               // 0..2047
        int c = idx >> 10, e = idx & 1023;
        int n = e >> 4, c8 = e & 15;
        cpa16(sb + OFF_WS0 + c*17408 + n*272 + c8*16, &g_ow1t[0][c][n*128 + c8*8]);
    }
    CPA_COMMIT();
    __syncthreads();

    if (tid < NC) {
        float s = 0.f;
        const float* row = xs + tid * Dd;
        #pragma unroll 8
        for (int d = 0; d < Dd; d++) { float v = row[d]; s = fmaf(v, v, s); }
        inorm[tid] = __fdiv_rn(1.f, __fsqrt_rn(s) + EPSF);
    }
    if (tid < 512) {
        int o = tid;
        int c = o >> 7, d = o & 127;
        float s = pb2[d];
        const float* ph = ph4 + c*64;
        #pragma unroll 8
        for (int tt = 0; tt < 64; tt++) s = fmaf(ph[tt], pW2[tt*128 + d], s);
        ptok4[o] = s;
    }
    __syncthreads();
    for (int o = tid; o < 1024; o += NT) {
        int c = o >> 8, q = o & 255;
        float s = 0.f;
        const float* pt = ptok4 + c*128;
        #pragma unroll 8
        for (int d = 0; d < 128; d++) s = fmaf(pt[d], fW1[(size_t)(1024 + d)*256 + q], s);
        pcon[o] = s;
    }
    __syncthreads();

    // ---- hid accumulator fragments: 16 warps as 2m x 8n ----
    const int mh = wid & 1;        // rows mh*32 .. +31
    const int nq = wid >> 1;       // cols nq*32 .. +31 (4 ntiles)
    float acc[2][4][4];
    #pragma unroll
    for (int mt2 = 0; mt2 < 2; mt2++) {
        int row = mh*32 + mt2*16 + g;
        int c0 = pcx[row], c1 = pcx[row + 8];
        #pragma unroll
        for (int nt = 0; nt < 4; nt++) {
            int q = nq*32 + nt*8 + t2;
            float cs0 = g_csum[q], cs1 = g_csum[q+1];
            acc[mt2][nt][0] = fb1[q]   + pcon[c0*256 + q]     + cs0;
            acc[mt2][nt][1] = fb1[q+1] + pcon[c0*256 + q + 1] + cs1;
            acc[mt2][nt][2] = fb1[q]   + pcon[c1*256 + q]     + cs0;
            acc[mt2][nt][3] = fb1[q+1] + pcon[c1*256 + q + 1] + cs1;
        }
    }

    #pragma unroll 1
    for (int k = 0; k < 8; k++) {
        const int w = mlp_idx[k];

        // ---- S1: issue G_hi -> WS1, G_lo -> WS2; feats -> fh/fl ----
        #pragma unroll
        for (int i = 0; i < 4; i++) {
            int idx = tid + i*NT;               // [256 n][72 k] bf16 panels
            int n = idx >> 3, c8 = idx & 7;
            cpa16(sb + OFF_WS1 + n*144 + c8*16, &g_gt[k][0][n*64 + c8*8]);
            cpa16(sb + OFF_WS2 + n*144 + c8*16, &g_gt[k][1][n*64 + c8*8]);
        }
        CPA_COMMIT();

        #pragma unroll 1
        for (int it = 0; it < 4; it++) {
            int o = tid + it*NT;
            int p = o >> 5, d4 = (o & 31) * 4;
            int ci = pi[p], cj = pj[p];
            float4 a4 = *(const float4*)(xs + ci*Dd + d4);
            float4 c4 = *(const float4*)(xs + cj*Dd + d4);
            float ni = inorm[ci], nj = inorm[cj];
            float f0 = featf(k, a4.x, c4.x, ni, nj);
            float f1 = featf(k, a4.y, c4.y, ni, nj);
            float f2 = featf(k, a4.z, c4.z, ni, nj);
            float f3 = featf(k, a4.w, c4.w, ni, nj);
            u32 h01, l01, h23, l23;
            split2(f0, f1, h01, l01);
            split2(f2, f3, h23, l23);
            int widx = p*68 + d4/2;
            *(uint2*)(fhw + widx) = make_uint2(h01, h23);
            *(uint2*)(flw + widx) = make_uint2(l01, l23);
        }
        CPA_WAIT0();            // W1(k) (prefetched last phase) + G panels
        __syncthreads();

        // ---- S2: h = relu(feats @ W1 + b1): 16 warps as 4m x 4n (B = WS0) ----
        {
            const int mt = wid >> 2, nh = wid & 3;
            const int arow = mt*16 + g;
            const u32* w1h = ws0w;                // [64][68] u32 rows
            const u32* w1l = ws0w + 4352;         // +17408B
            float hacc[2][4];
            #pragma unroll
            for (int nt = 0; nt < 2; nt++)
                #pragma unroll
                for (int e = 0; e < 4; e++) hacc[nt][e] = 0.f;
            #pragma unroll 1
            for (int ks = 0; ks < 8; ks++) {
                int base0 = arow*68 + ks*8 + t;
                int base1 = base0 + 8*68;
                u32 ah0 = fhw[base0], ah1 = fhw[base1], ah2 = fhw[base0+4], ah3 = fhw[base1+4];
                u32 al0 = flw[base0], al1 = flw[base1], al2 = flw[base0+4], al3 = flw[base1+4];
                #pragma unroll
                for (int nt = 0; nt < 2; nt++) {
                    int bn = nh*16 + nt*8 + g;
                    int bidx = bn*68 + ks*8 + t;
                    u32 bh0 = w1h[bidx], bh1 = w1h[bidx+4];
                    u32 bl0 = w1l[bidx], bl1 = w1l[bidx+4];
                    mma16816(hacc[nt], ah0, ah1, ah2, ah3, bh0, bh1);
                    mma16816(hacc[nt], al0, al1, al2, al3, bh0, bh1);
                    mma16816(hacc[nt], ah0, ah1, ah2, ah3, bl0, bl1);
                }
            }
            #pragma unroll
            for (int nt = 0; nt < 2; nt++) {
                int col = nh*16 + nt*8 + t2;
                float b0 = ob1[w*64 + col], b1v = ob1[w*64 + col + 1];
                float v0 = hacc[nt][0] + b0, v1 = hacc[nt][1] + b1v;
                float v2 = hacc[nt][2] + b0, v3 = hacc[nt][3] + b1v;
                v0 = v0 > 0.f ? v0 : 0.f; v1 = v1 > 0.f ? v1 : 0.f;
                v2 = v2 > 0.f ? v2 : 0.f; v3 = v3 > 0.f ? v3 : 0.f;
                u32 hp, lp;
                int cw = col/2;
                split2(v0, v1, hp, lp);
                hhw[arow*36 + cw] = hp; hlw[arow*36 + cw] = lp;
                split2(v2, v3, hp, lp);
                hhw[(arow+8)*36 + cw] = hp; hlw[(arow+8)*36 + cw] = lp;
            }
        }
        __syncthreads();

        // ---- S3: prefetch W1(k+1) -> WS0; merged hid GEMM (3 terms, B = WS1+WS2) ----
        if (k < 7) {
            const int wn = mlp_idx[k+1];
            #pragma unroll
            for (int i = 0; i < 4; i++) {
                int idx = tid + i*NT;
                int c = idx >> 10, e = idx & 1023;
                int n = e >> 4, c8 = e & 15;
                cpa16(sb + OFF_WS0 + c*17408 + n*272 + c8*16, &g_ow1t[wn][c][n*128 + c8*8]);
            }
            CPA_COMMIT();
        }
        #pragma unroll 1
        for (int ks = 0; ks < 4; ks++) {
            u32 ah[2][4], al[2][4];
            #pragma unroll
            for (int mt2 = 0; mt2 < 2; mt2++) {
                int row = mh*32 + mt2*16 + g;
                int base0 = row*36 + ks*8 + t;
                int base1 = base0 + 8*36;
                ah[mt2][0] = hhw[base0]; ah[mt2][1] = hhw[base1];
                ah[mt2][2] = hhw[base0+4]; ah[mt2][3] = hhw[base1+4];
                al[mt2][0] = hlw[base0]; al[mt2][1] = hlw[base1];
                al[mt2][2] = hlw[base0+4]; al[mt2][3] = hlw[base1+4];
            }
            #pragma unroll
            for (int nt = 0; nt < 4; nt++) {
                int bn = nq*32 + nt*8 + g;
                int bidx = bn*36 + ks*8 + t;
                u32 bh0 = ws1w[bidx], bh1 = ws1w[bidx+4];
                u32 bl0 = ws2w[bidx], bl1 = ws2w[bidx+4];
                #pragma unroll
                for (int mt2 = 0; mt2 < 2; mt2++) {
                    mma16816(acc[mt2][nt], ah[mt2][0], ah[mt2][1], ah[mt2][2], ah[mt2][3], bh0, bh1);
                    mma16816(acc[mt2][nt], al[mt2][0], al[mt2][1], al[mt2][2], al[mt2][3], bh0, bh1);
                    mma16816(acc[mt2][nt], ah[mt2][0], ah[mt2][1], ah[mt2][2], ah[mt2][3], bl0, bl1);
                }
            }
        }
        CPA_WAIT0();
        __syncthreads();
    }

    // ---- F1: hid epilogue -> bf16 hi/lo panels; stage fW2 kc0 hi/lo + kc1 hi ----
    u32* hidh = (u32*)(smc + OFF_HIDH);   // stride 132 u32
    u32* hidl = (u32*)(smc + OFF_HIDL);
    #pragma unroll
    for (int i = 0; i < 4; i++) {         // [128][136] bf16 panels
        int idx = tid + i*NT;
        int n = idx >> 4, c8 = idx & 15;
        cpa16(sb + OFF_WS0 + n*272 + c8*16, &g_fw2t[0][n*256 + c8*8]);
        cpa16(sb + OFF_WS1 + n*272 + c8*16, &g_fw2t[1][n*256 + c8*8]);
        cpa16(sb + OFF_WS2 + n*272 + c8*16, &g_fw2t[0][n*256 + 128 + c8*8]);
    }
    CPA_COMMIT();
    #pragma unroll
    for (int mt2 = 0; mt2 < 2; mt2++) {
        #pragma unroll
        for (int nt = 0; nt < 4; nt++) {
            int row = mh*32 + mt2*16 + g;
            float v0 = acc[mt2][nt][0] > 0.f ? acc[mt2][nt][0] : 0.f;
            float v1 = acc[mt2][nt][1] > 0.f ? acc[mt2][nt][1] : 0.f;
            float v2 = acc[mt2][nt][2] > 0.f ? acc[mt2][nt][2] : 0.f;
            float v3 = acc[mt2][nt][3] > 0.f ? acc[mt2][nt][3] : 0.f;
            int cw = nq*16 + nt*4 + t;
            u32 hp, lp;
            split2(v0, v1, hp, lp);
            hidh[row*132 + cw] = hp; hidl[row*132 + cw] = lp;
            split2(v2, v3, hp, lp);
            hidh[(row+8)*132 + cw] = hp; hidl[(row+8)*132 + cw] = lp;
        }
    }
    CPA_WAIT0();
    __syncthreads();

    // ---- F2: out = relu(hid) @ fW2 + fb2 via mma: 4m x 4n(32) ----
    {
        const int mt = wid >> 2, nh = wid & 3;
        const int arow = mt*16 + g;
        float acc2[4][4];
        #pragma unroll
        for (int nt = 0; nt < 4; nt++)
            #pragma unroll
            for (int e = 0; e < 4; e++) acc2[nt][e] = 0.f;

        // kc0: 3-term (hi = WS0, lo = WS1)
        #pragma unroll 1
        for (int ks = 0; ks < 8; ks++) {
            int base0 = arow*132 + ks*8 + t;
            int base1 = base0 + 8*132;
            u32 ah0 = hidh[base0], ah1 = hidh[base1], ah2 = hidh[base0+4], ah3 = hidh[base1+4];
            u32 al0 = hidl[base0], al1 = hidl[base1], al2 = hidl[base0+4], al3 = hidl[base1+4];
            #pragma unroll
            for (int nt = 0; nt < 4; nt++) {
                int bn = nh*32 + nt*8 + g;
                int bidx = bn*68 + ks*8 + t;
                u32 bh0 = ws0w[bidx], bh1 = ws0w[bidx+4];
                u32 bl0 = ws1w[bidx], bl1 = ws1w[bidx+4];
                mma16816(acc2[nt], ah0, ah1, ah2, ah3, bh0, bh1);
                mma16816(acc2[nt], al0, al1, al2, al3, bh0, bh1);
                mma16816(acc2[nt], ah0, ah1, ah2, ah3, bl0, bl1);
            }
        }
        __syncthreads();   // everyone done reading WS0/WS1 (kc0 panels)

        // stage kc1 lo -> WS0 (overlaps with kc1 hi-term mma below)
        #pragma unroll
        for (int i = 0; i < 4; i++) {
            int idx = tid + i*NT;
            int n = idx >> 4, c8 = idx & 15;
            cpa16(sb + OFF_WS0 + n*272 + c8*16, &g_fw2t[1][n*256 + 128 + c8*8]);
        }
        CPA_COMMIT();

        // kc1 hi-terms (hi = WS2)
        #pragma unroll 1
        for (int ks = 0; ks < 8; ks++) {
            int base0 = arow*132 + 64 + ks*8 + t;
            int base1 = base0 + 8*132;
            u32 ah0 = hidh[base0], ah1 = hidh[base1], ah2 = hidh[base0+4], ah3 = hidh[base1+4];
            u32 al0 = hidl[base0], al1 = hidl[base1], al2 = hidl[base0+4], al3 = hidl[base1+4];
            #pragma unroll
            for (int nt = 0; nt < 4; nt++) {
                int bn = nh*32 + nt*8 + g;
                int bidx = bn*68 + ks*8 + t;
                u32 bh0 = ws2w[bidx], bh1 = ws2w[bidx+4];
                mma16816(acc2[nt], ah0, ah1, ah2, ah3, bh0, bh1);
                mma16816(acc2[nt], al0, al1, al2, al3, bh0, bh1);
            }
        }
        CPA_WAIT0();
        __syncthreads();

        // kc1 lo-term (lo = WS0)
        #pragma unroll 1
        for (int ks = 0; ks < 8; ks++) {
            int base0 = arow*132 + 64 + ks*8 + t;
            int base1 = base0 + 8*132;
            u32 ah0 = hidh[base0], ah1 = hidh[base1], ah2 = hidh[base0+4], ah3 = hidh[base1+4];
            #pragma unroll
            for (int nt = 0; nt < 4; nt++) {
                int bn = nh*32 + nt*8 + g;
                int bidx = bn*68 + ks*8 + t;
                u32 bl0 = ws0w[bidx], bl1 = ws0w[bidx+4];
                mma16816(acc2[nt], ah0, ah1, ah2, ah3, bl0, bl1);
            }
        }

        // epilogue: + fb2, store to gmem
        #pragma unroll
        for (int nt = 0; nt < 4; nt++) {
            int col = nh*32 + nt*8 + t2;
            float b0 = fb2[col], b1v = fb2[col + 1];
            int r0 = mt*16 + g, r1 = r0 + 8;
            if (p0 + r0 < Pp) {
                float2 v = make_float2(acc2[nt][0] + b0, acc2[nt][1] + b1v);
                *(float2*)(out + ((size_t)(b*Pp + p0 + r0))*128 + col) = v;
            }
            if (p0 + r1 < Pp) {
                float2 v = make_float2(acc2[nt][2] + b0, acc2[nt][3] + b1v);
                *(float2*)(out + ((size_t)(b*Pp + p0 + r1))*128 + col) = v;
            }
        }
    }
}

extern "C" void kernel_launch(void* const* d_in, const int* in_sizes, int n_in,
                              void* d_out, int out_size) {
    const float* x        = (const float*)d_in[0];
    const int*   presence = (const int*)d_in[1];
    const int*   idx_i    = (const int*)d_in[2];
    const int*   idx_j    = (const int*)d_in[3];
    const float* oW1      = (const float*)d_in[4];
    const float* ob1      = (const float*)d_in[5];
    const float* oW2      = (const float*)d_in[6];
    const float* ob2      = (const float*)d_in[7];
    const float* pW1      = (const float*)d_in[8];
    const float* pb1      = (const float*)d_in[9];
    const float* pW2      = (const float*)d_in[10];
    const float* pb2      = (const float*)d_in[11];
    const float* fW1      = (const float*)d_in[12];
    const float* fb1      = (const float*)d_in[13];
    const float* fW2      = (const float*)d_in[14];
    const float* fb2      = (const float*)d_in[15];

    conv_kernel<<<1024, 256>>>(fW1, oW1, oW2, ob2, fW2);

    cudaFuncSetAttribute(dre_kernel, cudaFuncAttributeMaxDynamicSharedMemorySize, SMEM_BYTES);
    dre_kernel<<<2048, NT, SMEM_BYTES>>>(x, presence, idx_i, idx_j,
                                         oW1, ob1, oW2, ob2,
                                         pW1, pb1, pW2, pb2,
                                         fW1, fb1, fW2, fb2,
                                         (float*)d_out);
}